// round 1
// baseline (speedup 1.0000x reference)
#include <cuda_runtime.h>
#include <math.h>

// Problem constants
#define Bc   2
#define Tc   2048
#define Dc   1024
#define Hc   16
#define DHc  64
#define Cc   128
#define BT   4096   // B*T

// ---------------- scratch (no allocations allowed) ----------------
__device__ float g_ck[BT * Cc];
__device__ float g_cv[BT * Cc];
__device__ float g_kf[BT * Dc];
__device__ float g_vf[BT * Dc];
__device__ float g_q [BT * Dc];   // [B,H,T,DH]
__device__ float g_kh[BT * Dc];   // [B,H,T,DH]
__device__ float g_vh[BT * Dc];   // [B,H,T,DH]
__device__ float g_ao[BT * Dc];   // attention out in [B,T,D]

// ---------------- generic tiled SGEMM: C = A@B + bias ----------------
// BM=BN=64, BK=16, 256 threads, 4x4 per thread
template<int BM, int BN, int BK>
__global__ void sgemm_bias(const float* __restrict__ A,
                           const float* __restrict__ Bm,
                           const float* __restrict__ bias,
                           float* __restrict__ C,
                           int M, int N, int K) {
    __shared__ float As[BK][BM + 4];
    __shared__ float Bs[BK][BN + 4];

    const int tid = threadIdx.x;
    const int tx  = tid & 15;   // 0..15
    const int ty  = tid >> 4;   // 0..15
    const int row0 = blockIdx.y * BM;
    const int col0 = blockIdx.x * BN;

    float acc[4][4] = {};

    for (int k0 = 0; k0 < K; k0 += BK) {
        #pragma unroll
        for (int i = tid; i < BM * BK; i += 256) {
            int m = i / BK, kk = i % BK;
            As[kk][m] = A[(long)(row0 + m) * K + k0 + kk];
        }
        #pragma unroll
        for (int i = tid; i < BK * BN; i += 256) {
            int kk = i / BN, n = i % BN;
            Bs[kk][n] = Bm[(long)(k0 + kk) * N + col0 + n];
        }
        __syncthreads();

        #pragma unroll
        for (int kk = 0; kk < BK; kk++) {
            float a[4], b[4];
            *(float4*)a = *(const float4*)&As[kk][ty * 4];
            *(float4*)b = *(const float4*)&Bs[kk][tx * 4];
            #pragma unroll
            for (int i = 0; i < 4; i++)
                #pragma unroll
                for (int j = 0; j < 4; j++)
                    acc[i][j] += a[i] * b[j];
        }
        __syncthreads();
    }

    #pragma unroll
    for (int i = 0; i < 4; i++) {
        int r = row0 + ty * 4 + i;
        #pragma unroll
        for (int j = 0; j < 4; j++) {
            int c = col0 + tx * 4 + j;
            C[(long)r * N + c] = acc[i][j] + bias[c];
        }
    }
}

// ---------------- RoPE + head split ----------------
// Produces q,k (with rope) and v in [B,H,T,DH] layout.
__global__ void prepare_qkv(const float* __restrict__ x,
                            const float* __restrict__ kf,
                            const float* __restrict__ vf,
                            float* __restrict__ qh,
                            float* __restrict__ kh,
                            float* __restrict__ vh) {
    int idx = blockIdx.x * blockDim.x + threadIdx.x;  // < BT*Dc
    int d = idx & 63;
    int t = (idx >> 6) & 2047;
    int h = (idx >> 17) & 15;
    int b = idx >> 21;
    long src = ((long)(b * Tc + t)) * Dc + h * DHc + d;

    int i2 = d & 31;  // d % (DH/2)
    float inv_freq = powf(10000.0f, -(float)i2 / 32.0f);
    float ang = (float)t * inv_freq;
    float sv, cv;
    sincosf(ang, &sv, &cv);

    float xv = x[src];
    float xr = (d < 32) ? -x[src + 32] : x[src - 32];
    qh[idx] = xv * cv + xr * sv;

    float kv = kf[src];
    float kr = (d < 32) ? -kf[src + 32] : kf[src - 32];
    kh[idx] = kv * cv + kr * sv;

    vh[idx] = vf[src];
}

// ---------------- flash-style attention ----------------
// Per block: one (b,h) and a 64-row query tile; loop over 64-key tiles with
// online softmax. 256 threads, 4x4 register blocking for both GEMMs.
// Dynamic smem layout (stride 68 floats keeps float4 alignment):
//   qs[64][68] (q transposed: qs[d][m])
//   ks[64][68] (k transposed: ks[d][n])
//   vs[64][68] (vs[n][d])
//   ps[64][68] (probabilities ps[m][n])
#define ATT_STRIDE 68
#define ATT_SMEM_FLOATS (4 * 64 * ATT_STRIDE)

__global__ void attn_kernel(const float* __restrict__ qh,
                            const float* __restrict__ kh,
                            const float* __restrict__ vh,
                            float* __restrict__ out) {
    extern __shared__ float sm[];
    float* qs = sm;
    float* ks = sm + 64 * ATT_STRIDE;
    float* vs = sm + 2 * 64 * ATT_STRIDE;
    float* ps = sm + 3 * 64 * ATT_STRIDE;

    const int tid = threadIdx.x;
    const int tx  = tid & 15;
    const int ty  = tid >> 4;
    const int bh  = blockIdx.y;
    const int b   = bh >> 4;
    const int h   = bh & 15;

    const float* qp = qh + ((long)bh * Tc + blockIdx.x * 64) * DHc;
    const float* kp = kh + (long)bh * Tc * DHc;
    const float* vp = vh + (long)bh * Tc * DHc;

    // load q tile transposed
    for (int i = tid; i < 64 * 64; i += 256) {
        int m = i >> 6, d = i & 63;
        qs[d * ATT_STRIDE + m] = qp[i];
    }

    float m_i[4], l_i[4], o[4][4];
    #pragma unroll
    for (int i = 0; i < 4; i++) {
        m_i[i] = -1e30f; l_i[i] = 0.0f;
        #pragma unroll
        for (int j = 0; j < 4; j++) o[i][j] = 0.0f;
    }
    __syncthreads();

    for (int kt = 0; kt < Tc; kt += 64) {
        // load k (transposed) and v tiles
        for (int i = tid; i < 64 * 64; i += 256) {
            int n = i >> 6, d = i & 63;
            float kval = kp[kt * 64 + i];
            float vval = vp[kt * 64 + i];
            ks[d * ATT_STRIDE + n] = kval;
            vs[n * ATT_STRIDE + d] = vval;
        }
        __syncthreads();

        // S = Q @ K^T  (64x64x64)
        float s[4][4] = {};
        #pragma unroll
        for (int d = 0; d < 64; d++) {
            float a[4], bb[4];
            *(float4*)a  = *(const float4*)&qs[d * ATT_STRIDE + ty * 4];
            *(float4*)bb = *(const float4*)&ks[d * ATT_STRIDE + tx * 4];
            #pragma unroll
            for (int i = 0; i < 4; i++)
                #pragma unroll
                for (int j = 0; j < 4; j++)
                    s[i][j] += a[i] * bb[j];
        }

        // online softmax per row (row owned by 16 threads: same ty, all tx)
        #pragma unroll
        for (int i = 0; i < 4; i++) {
            float mt = -1e30f;
            #pragma unroll
            for (int j = 0; j < 4; j++) {
                s[i][j] *= 0.125f;   // 1/sqrt(64)
                mt = fmaxf(mt, s[i][j]);
            }
            mt = fmaxf(mt, __shfl_xor_sync(0xffffffffu, mt, 1));
            mt = fmaxf(mt, __shfl_xor_sync(0xffffffffu, mt, 2));
            mt = fmaxf(mt, __shfl_xor_sync(0xffffffffu, mt, 4));
            mt = fmaxf(mt, __shfl_xor_sync(0xffffffffu, mt, 8));

            float mnew = fmaxf(m_i[i], mt);
            float corr = __expf(m_i[i] - mnew);
            float lsum = 0.0f;
            #pragma unroll
            for (int j = 0; j < 4; j++) {
                float p = __expf(s[i][j] - mnew);
                ps[(ty * 4 + i) * ATT_STRIDE + tx * 4 + j] = p;
                lsum += p;
            }
            lsum += __shfl_xor_sync(0xffffffffu, lsum, 1);
            lsum += __shfl_xor_sync(0xffffffffu, lsum, 2);
            lsum += __shfl_xor_sync(0xffffffffu, lsum, 4);
            lsum += __shfl_xor_sync(0xffffffffu, lsum, 8);

            l_i[i] = l_i[i] * corr + lsum;
            m_i[i] = mnew;
            #pragma unroll
            for (int j = 0; j < 4; j++) o[i][j] *= corr;
        }
        __syncwarp();   // ps rows are produced/consumed within one warp

        // O += P @ V  (64x64x64)
        #pragma unroll 8
        for (int kk = 0; kk < 64; kk++) {
            float bb[4];
            *(float4*)bb = *(const float4*)&vs[kk * ATT_STRIDE + tx * 4];
            #pragma unroll
            for (int i = 0; i < 4; i++) {
                float p = ps[(ty * 4 + i) * ATT_STRIDE + kk];
                #pragma unroll
                for (int j = 0; j < 4; j++)
                    o[i][j] += p * bb[j];
            }
        }
        __syncthreads();
    }

    // epilogue: normalize and write to [B,T,D] layout
    #pragma unroll
    for (int i = 0; i < 4; i++) {
        float inv = 1.0f / l_i[i];
        int t = blockIdx.x * 64 + ty * 4 + i;
        long off = ((long)b * Tc + t) * Dc + h * DHc + tx * 4;
        #pragma unroll
        for (int j = 0; j < 4; j++)
            out[off + j] = o[i][j] * inv;
    }
}

// ---------------- launch ----------------
extern "C" void kernel_launch(void* const* d_in, const int* in_sizes, int n_in,
                              void* d_out, int out_size) {
    const float* x    = (const float*)d_in[0];
    const float* w_dk = (const float*)d_in[1];
    const float* b_dk = (const float*)d_in[2];
    const float* w_dv = (const float*)d_in[3];
    const float* b_dv = (const float*)d_in[4];
    const float* w_uk = (const float*)d_in[5];
    const float* b_uk = (const float*)d_in[6];
    const float* w_uv = (const float*)d_in[7];
    const float* b_uv = (const float*)d_in[8];
    const float* w_o  = (const float*)d_in[9];
    const float* b_o  = (const float*)d_in[10];
    float* out = (float*)d_out;

    float *ck, *cv, *kf, *vf, *q, *kh, *vh, *ao;
    cudaGetSymbolAddress((void**)&ck, g_ck);
    cudaGetSymbolAddress((void**)&cv, g_cv);
    cudaGetSymbolAddress((void**)&kf, g_kf);
    cudaGetSymbolAddress((void**)&vf, g_vf);
    cudaGetSymbolAddress((void**)&q,  g_q);
    cudaGetSymbolAddress((void**)&kh, g_kh);
    cudaGetSymbolAddress((void**)&vh, g_vh);
    cudaGetSymbolAddress((void**)&ao, g_ao);

    dim3 blk(256);

    // low-rank down-projections: (BT x D) @ (D x C)
    sgemm_bias<64,64,16><<<dim3(Cc/64, BT/64), blk>>>(x, w_dk, b_dk, ck, BT, Cc, Dc);
    sgemm_bias<64,64,16><<<dim3(Cc/64, BT/64), blk>>>(x, w_dv, b_dv, cv, BT, Cc, Dc);

    // up-projections: (BT x C) @ (C x D)
    sgemm_bias<64,64,16><<<dim3(Dc/64, BT/64), blk>>>(ck, w_uk, b_uk, kf, BT, Dc, Cc);
    sgemm_bias<64,64,16><<<dim3(Dc/64, BT/64), blk>>>(cv, w_uv, b_uv, vf, BT, Dc, Cc);

    // RoPE + head split
    prepare_qkv<<<(BT * Dc) / 256, 256>>>(x, kf, vf, q, kh, vh);

    // attention
    const int att_smem = ATT_SMEM_FLOATS * sizeof(float);
    cudaFuncSetAttribute(attn_kernel, cudaFuncAttributeMaxDynamicSharedMemorySize, att_smem);
    attn_kernel<<<dim3(Tc/64, Bc*Hc), blk, att_smem>>>(q, kh, vh, ao);

    // output projection: (BT x D) @ (D x D)
    sgemm_bias<64,64,16><<<dim3(Dc/64, BT/64), blk>>>(ao, w_o, b_o, out, BT, Dc, Dc);
}

// round 3
// speedup vs baseline: 2.1571x; 2.1571x over previous
#include <cuda_runtime.h>
#include <math.h>
#include <stdint.h>

// Problem constants
#define Bc   2
#define Tc   2048
#define Dc   1024
#define Hc   16
#define DHc  64
#define Cc   128
#define BT   4096   // B*T

// ---------------- scratch (no allocations allowed) ----------------
__device__ float g_ck[BT * Cc];
__device__ float g_cv[BT * Cc];
__device__ float g_kf[BT * Dc];
__device__ float g_vf[BT * Dc];
__device__ float g_q [BT * Dc];   // [B,H,T,DH]
__device__ float g_kh[BT * Dc];   // [B,H,T,DH]
__device__ float g_vh[BT * Dc];   // [B,H,T,DH]
__device__ float g_ao[BT * Dc];   // attention out in [B,T,D]

// ---------------- helpers ----------------
__device__ __forceinline__ unsigned f2tf32(float f) {
    unsigned u;
    asm("cvt.rna.tf32.f32 %0, %1;" : "=r"(u) : "f"(f));
    return u;
}

__device__ __forceinline__ void mma_tf32(float c[4], const unsigned a[4], const unsigned b[2]) {
    asm volatile(
        "mma.sync.aligned.m16n8k8.row.col.f32.tf32.tf32.f32 "
        "{%0,%1,%2,%3}, {%4,%5,%6,%7}, {%8,%9}, {%0,%1,%2,%3};"
        : "+f"(c[0]), "+f"(c[1]), "+f"(c[2]), "+f"(c[3])
        : "r"(a[0]), "r"(a[1]), "r"(a[2]), "r"(a[3]), "r"(b[0]), "r"(b[1]));
}

// ---------------- tf32 tensor-core GEMM: C = A@B + bias ----------------
// BM=128, BN=128, BK=16, 256 threads (8 warps), warp tile 32x64.
// z-dim selects between two independent problems (for fused dual launches).
#define GA_PAD 20
#define GB_PAD 136

__global__ void mma_gemm(const float* __restrict__ A0, const float* __restrict__ B0,
                         const float* __restrict__ bi0, float* __restrict__ C0,
                         const float* __restrict__ A1, const float* __restrict__ B1,
                         const float* __restrict__ bi1, float* __restrict__ C1,
                         int M, int N, int K) {
    const float* A    = blockIdx.z ? A1 : A0;
    const float* Bm   = blockIdx.z ? B1 : B0;
    const float* bias = blockIdx.z ? bi1 : bi0;
    float*       C    = blockIdx.z ? C1 : C0;

    __shared__ unsigned As[128][GA_PAD];   // [m][k], tf32 bits
    __shared__ unsigned Bs[16][GB_PAD];    // [k][n], tf32 bits

    const int tid  = threadIdx.x;
    const int lane = tid & 31;
    const int wid  = tid >> 5;
    const int wm   = wid & 3;        // 0..3  -> m offset 32*wm
    const int wn   = wid >> 2;       // 0..1  -> n offset 64*wn
    const int g    = lane >> 2;      // groupID 0..7
    const int q    = lane & 3;       // thread-in-group 0..3

    const int row0 = blockIdx.y * 128;
    const int col0 = blockIdx.x * 128;

    float acc[2][8][4];
    #pragma unroll
    for (int mi = 0; mi < 2; mi++)
        #pragma unroll
        for (int j = 0; j < 8; j++)
            #pragma unroll
            for (int e = 0; e < 4; e++) acc[mi][j][e] = 0.0f;

    for (int k0 = 0; k0 < K; k0 += 16) {
        // load A tile 128x16 (float4 along K), convert to tf32, store [m][k]
        #pragma unroll
        for (int i = tid; i < 512; i += 256) {
            int row = i >> 2, c4 = i & 3;
            float4 v = *(const float4*)(A + (long)(row0 + row) * K + k0 + 4 * c4);
            uint4 u = make_uint4(f2tf32(v.x), f2tf32(v.y), f2tf32(v.z), f2tf32(v.w));
            *(uint4*)&As[row][4 * c4] = u;
        }
        // load B tile 16x128 (float4 along N), convert, store [k][n]
        #pragma unroll
        for (int i = tid; i < 512; i += 256) {
            int kr = i >> 5, n4 = i & 31;
            float4 v = *(const float4*)(Bm + (long)(k0 + kr) * N + col0 + 4 * n4);
            uint4 u = make_uint4(f2tf32(v.x), f2tf32(v.y), f2tf32(v.z), f2tf32(v.w));
            *(uint4*)&Bs[kr][4 * n4] = u;
        }
        __syncthreads();

        #pragma unroll
        for (int kk = 0; kk < 2; kk++) {
            unsigned a[2][4];
            #pragma unroll
            for (int mi = 0; mi < 2; mi++) {
                int m = 32 * wm + 16 * mi;
                a[mi][0] = As[m + g    ][8 * kk + q];
                a[mi][1] = As[m + g + 8][8 * kk + q];
                a[mi][2] = As[m + g    ][8 * kk + q + 4];
                a[mi][3] = As[m + g + 8][8 * kk + q + 4];
            }
            #pragma unroll
            for (int j = 0; j < 8; j++) {
                unsigned b[2];
                b[0] = Bs[8 * kk + q    ][64 * wn + 8 * j + g];
                b[1] = Bs[8 * kk + q + 4][64 * wn + 8 * j + g];
                mma_tf32(acc[0][j], a[0], b);
                mma_tf32(acc[1][j], a[1], b);
            }
        }
        __syncthreads();
    }

    // epilogue with bias
    #pragma unroll
    for (int mi = 0; mi < 2; mi++) {
        int row = row0 + 32 * wm + 16 * mi + g;
        #pragma unroll
        for (int j = 0; j < 8; j++) {
            int col = col0 + 64 * wn + 8 * j + 2 * q;
            float b0 = bias[col], b1 = bias[col + 1];
            *(float2*)&C[(long)row * N + col] =
                make_float2(acc[mi][j][0] + b0, acc[mi][j][1] + b1);
            *(float2*)&C[(long)(row + 8) * N + col] =
                make_float2(acc[mi][j][2] + b0, acc[mi][j][3] + b1);
        }
    }
}

// ---------------- RoPE + head split ----------------
__global__ void prepare_qkv(const float* __restrict__ x,
                            const float* __restrict__ kf,
                            const float* __restrict__ vf,
                            float* __restrict__ qh,
                            float* __restrict__ kh,
                            float* __restrict__ vh) {
    int idx = blockIdx.x * blockDim.x + threadIdx.x;  // < BT*Dc
    int d = idx & 63;
    int t = (idx >> 6) & 2047;
    int h = (idx >> 17) & 15;
    int b = idx >> 21;
    long src = ((long)(b * Tc + t)) * Dc + h * DHc + d;

    int i2 = d & 31;
    float inv_freq = powf(10000.0f, -(float)i2 / 32.0f);
    float ang = (float)t * inv_freq;
    float sv, cv;
    sincosf(ang, &sv, &cv);

    float xv = x[src];
    float xr = (d < 32) ? -x[src + 32] : x[src - 32];
    qh[idx] = xv * cv + xr * sv;

    float kv = kf[src];
    float kr = (d < 32) ? -kf[src + 32] : kf[src - 32];
    kh[idx] = kv * cv + kr * sv;

    vh[idx] = vf[src];
}

// ---------------- flash attention with tf32 mma ----------------
// Block: 256 threads (8 warps), one (b,h), 128 query rows (16 per warp).
// Q kept in registers as tf32 A-fragments. K/V staged in smem (tf32 bits).
// P round-trips through warp-private smem to become A-fragments.
// Dynamic smem layout (floats/unsigned, all conflict-free strides):
//   Ks[64][68], Vs[64][72], Ps[8][16][68]
#define KS_STRIDE 68
#define VS_STRIDE 72
#define PS_STRIDE 68
#define ATT_SMEM_BYTES ((64 * KS_STRIDE + 64 * VS_STRIDE + 8 * 16 * PS_STRIDE) * 4)

__global__ void attn_kernel(const float* __restrict__ qh,
                            const float* __restrict__ kh,
                            const float* __restrict__ vh,
                            float* __restrict__ out) {
    extern __shared__ unsigned smattn[];
    unsigned* Ks = smattn;                              // [64][KS_STRIDE]
    unsigned* Vs = Ks + 64 * KS_STRIDE;                 // [64][VS_STRIDE]
    unsigned* Psb = Vs + 64 * VS_STRIDE;                // [8][16][PS_STRIDE]

    const int tid  = threadIdx.x;
    const int lane = tid & 31;
    const int w    = tid >> 5;        // warp 0..7 -> q rows [16w,16w+16)
    const int g    = lane >> 2;
    const int q    = lane & 3;

    unsigned* Ps = Psb + w * 16 * PS_STRIDE;            // warp-private [16][PS_STRIDE]

    const int bh = blockIdx.y;
    const int b  = bh >> 4;
    const int h  = bh & 15;
    const int t0 = blockIdx.x * 128;

    const float* qp = qh + ((long)bh * Tc + t0) * DHc;
    const float* kp = kh + (long)bh * Tc * DHc;
    const float* vp = vh + (long)bh * Tc * DHc;

    // Q fragments for all 8 k-steps (DH=64), held in registers
    unsigned qa[8][4];
    #pragma unroll
    for (int kk = 0; kk < 8; kk++) {
        qa[kk][0] = f2tf32(qp[(16 * w + g    ) * 64 + 8 * kk + q    ]);
        qa[kk][1] = f2tf32(qp[(16 * w + g + 8) * 64 + 8 * kk + q    ]);
        qa[kk][2] = f2tf32(qp[(16 * w + g    ) * 64 + 8 * kk + q + 4]);
        qa[kk][3] = f2tf32(qp[(16 * w + g + 8) * 64 + 8 * kk + q + 4]);
    }

    float o[8][4];
    #pragma unroll
    for (int j = 0; j < 8; j++)
        #pragma unroll
        for (int e = 0; e < 4; e++) o[j][e] = 0.0f;
    float m_i[2] = {-1e30f, -1e30f};
    float l_i[2] = {0.0f, 0.0f};

    for (int kt = 0; kt < Tc; kt += 64) {
        __syncthreads();   // previous PV done reading Vs
        // load K/V tiles (64x64 each) as tf32 bits
        #pragma unroll
        for (int i = tid; i < 1024; i += 256) {
            int n = i >> 4, d4 = i & 15;
            float4 kv = *(const float4*)(kp + (long)(kt + n) * 64 + 4 * d4);
            float4 vv = *(const float4*)(vp + (long)(kt + n) * 64 + 4 * d4);
            *(uint4*)&Ks[n * KS_STRIDE + 4 * d4] =
                make_uint4(f2tf32(kv.x), f2tf32(kv.y), f2tf32(kv.z), f2tf32(kv.w));
            *(uint4*)&Vs[n * VS_STRIDE + 4 * d4] =
                make_uint4(f2tf32(vv.x), f2tf32(vv.y), f2tf32(vv.z), f2tf32(vv.w));
        }
        __syncthreads();

        // S = Q @ K^T  (16x64 per warp)
        float s[8][4];
        #pragma unroll
        for (int j = 0; j < 8; j++)
            #pragma unroll
            for (int e = 0; e < 4; e++) s[j][e] = 0.0f;
        #pragma unroll
        for (int kk = 0; kk < 8; kk++) {
            #pragma unroll
            for (int j = 0; j < 8; j++) {
                unsigned bfr[2];
                bfr[0] = Ks[(8 * j + g) * KS_STRIDE + 8 * kk + q    ];
                bfr[1] = Ks[(8 * j + g) * KS_STRIDE + 8 * kk + q + 4];
                mma_tf32(s[j], qa[kk], bfr);
            }
        }

        // online softmax per row-half (rows g and g+8 of warp tile)
        #pragma unroll
        for (int hh = 0; hh < 2; hh++) {
            float mt = -1e30f;
            #pragma unroll
            for (int j = 0; j < 8; j++) {
                s[j][2 * hh]     *= 0.125f;
                s[j][2 * hh + 1] *= 0.125f;
                mt = fmaxf(mt, fmaxf(s[j][2 * hh], s[j][2 * hh + 1]));
            }
            mt = fmaxf(mt, __shfl_xor_sync(0xffffffffu, mt, 1));
            mt = fmaxf(mt, __shfl_xor_sync(0xffffffffu, mt, 2));

            float mnew = fmaxf(m_i[hh], mt);
            float corr = __expf(m_i[hh] - mnew);
            int r = hh ? (g + 8) : g;
            float lsum = 0.0f;
            #pragma unroll
            for (int j = 0; j < 8; j++) {
                float p0 = __expf(s[j][2 * hh]     - mnew);
                float p1 = __expf(s[j][2 * hh + 1] - mnew);
                lsum += p0 + p1;
                Ps[r * PS_STRIDE + 8 * j + 2 * q]     = f2tf32(p0);
                Ps[r * PS_STRIDE + 8 * j + 2 * q + 1] = f2tf32(p1);
            }
            lsum += __shfl_xor_sync(0xffffffffu, lsum, 1);
            lsum += __shfl_xor_sync(0xffffffffu, lsum, 2);

            l_i[hh] = l_i[hh] * corr + lsum;
            m_i[hh] = mnew;
            #pragma unroll
            for (int j = 0; j < 8; j++) {
                o[j][2 * hh]     *= corr;
                o[j][2 * hh + 1] *= corr;
            }
        }
        __syncwarp();

        // O += P @ V
        #pragma unroll
        for (int kk = 0; kk < 8; kk++) {
            unsigned pa[4];
            pa[0] = Ps[(g    ) * PS_STRIDE + 8 * kk + q    ];
            pa[1] = Ps[(g + 8) * PS_STRIDE + 8 * kk + q    ];
            pa[2] = Ps[(g    ) * PS_STRIDE + 8 * kk + q + 4];
            pa[3] = Ps[(g + 8) * PS_STRIDE + 8 * kk + q + 4];
            #pragma unroll
            for (int j = 0; j < 8; j++) {
                unsigned bfr[2];
                bfr[0] = Vs[(8 * kk + q    ) * VS_STRIDE + 8 * j + g];
                bfr[1] = Vs[(8 * kk + q + 4) * VS_STRIDE + 8 * j + g];
                mma_tf32(o[j], pa, bfr);
            }
        }
    }

    // epilogue: normalize, write to [B,T,D]
    float inv0 = 1.0f / l_i[0];
    float inv1 = 1.0f / l_i[1];
    int t_r0 = t0 + 16 * w + g;
    long base0 = ((long)b * Tc + t_r0) * Dc + h * DHc;
    long base1 = ((long)b * Tc + t_r0 + 8) * Dc + h * DHc;
    #pragma unroll
    for (int j = 0; j < 8; j++) {
        int col = 8 * j + 2 * q;
        *(float2*)&out[base0 + col] = make_float2(o[j][0] * inv0, o[j][1] * inv0);
        *(float2*)&out[base1 + col] = make_float2(o[j][2] * inv1, o[j][3] * inv1);
    }
}

// ---------------- launch ----------------
extern "C" void kernel_launch(void* const* d_in, const int* in_sizes, int n_in,
                              void* d_out, int out_size) {
    const float* x    = (const float*)d_in[0];
    const float* w_dk = (const float*)d_in[1];
    const float* b_dk = (const float*)d_in[2];
    const float* w_dv = (const float*)d_in[3];
    const float* b_dv = (const float*)d_in[4];
    const float* w_uk = (const float*)d_in[5];
    const float* b_uk = (const float*)d_in[6];
    const float* w_uv = (const float*)d_in[7];
    const float* b_uv = (const float*)d_in[8];
    const float* w_o  = (const float*)d_in[9];
    const float* b_o  = (const float*)d_in[10];
    float* out = (float*)d_out;

    float *ck, *cv, *kf, *vf, *qv, *kh, *vh, *ao;
    cudaGetSymbolAddress((void**)&ck, g_ck);
    cudaGetSymbolAddress((void**)&cv, g_cv);
    cudaGetSymbolAddress((void**)&kf, g_kf);
    cudaGetSymbolAddress((void**)&vf, g_vf);
    cudaGetSymbolAddress((void**)&qv, g_q);
    cudaGetSymbolAddress((void**)&kh, g_kh);
    cudaGetSymbolAddress((void**)&vh, g_vh);
    cudaGetSymbolAddress((void**)&ao, g_ao);

    dim3 blk(256);

    // down-projections (fused via z): (BT x 1024) @ (1024 x 128)
    mma_gemm<<<dim3(Cc / 128, BT / 128, 2), blk>>>(
        x, w_dk, b_dk, ck, x, w_dv, b_dv, cv, BT, Cc, Dc);

    // up-projections (fused via z): (BT x 128) @ (128 x 1024)
    mma_gemm<<<dim3(Dc / 128, BT / 128, 2), blk>>>(
        ck, w_uk, b_uk, kf, cv, w_uv, b_uv, vf, BT, Dc, Cc);

    // RoPE + head split
    prepare_qkv<<<(BT * Dc) / 256, 256>>>(x, kf, vf, qv, kh, vh);

    // attention
    static int attn_attr_set = 0;
    if (!attn_attr_set) {
        cudaFuncSetAttribute(attn_kernel, cudaFuncAttributeMaxDynamicSharedMemorySize,
                             ATT_SMEM_BYTES);
        attn_attr_set = 1;
    }
    attn_kernel<<<dim3(Tc / 128, Bc * Hc), blk, ATT_SMEM_BYTES>>>(qv, kh, vh, ao);

    // output projection: (BT x 1024) @ (1024 x 1024)
    mma_gemm<<<dim3(Dc / 128, BT / 128, 1), blk>>>(
        ao, w_o, b_o, out, ao, w_o, b_o, out, BT, Dc, Dc);
}

// round 4
// speedup vs baseline: 3.6482x; 1.6913x over previous
#include <cuda_runtime.h>
#include <math.h>
#include <stdint.h>

// Problem constants
#define Bc   2
#define Tc   2048
#define Dc   1024
#define Hc   16
#define DHc  64
#define Cc   128
#define BT   4096   // B*T

// ---------------- scratch (no allocations allowed) ----------------
__device__ float g_ck[BT * Cc];       // rounded tf32 bits
__device__ float g_cv[BT * Cc];       // rounded
__device__ float g_kf[BT * Dc];       // fp32 (pre-rope)
__device__ float g_vf[BT * Dc];       // fp32 (pre-headsplit)
__device__ float g_q [BT * Dc];       // [B,H,T,DH], rounded
__device__ float g_kh[BT * Dc];       // [B,H,T,DH], rounded
__device__ float g_vh[BT * Dc];       // [B,H,T,DH], rounded
__device__ float g_ao[BT * Dc];       // attention out [B,T,D], rounded
__device__ float g_xr[BT * Dc];       // x rounded
__device__ float g_wor[Dc * Dc];      // w_o rounded
__device__ float g_wdkr[Dc * Cc];
__device__ float g_wdvr[Dc * Cc];
__device__ float g_wukr[Cc * Dc];
__device__ float g_wuvr[Cc * Dc];

// ---------------- helpers ----------------
__device__ __forceinline__ unsigned f2tf32(float f) {
    unsigned u;
    asm("cvt.rna.tf32.f32 %0, %1;" : "=r"(u) : "f"(f));
    return u;
}
__device__ __forceinline__ float roundtf(float f) {
    return __uint_as_float(f2tf32(f));
}

__device__ __forceinline__ void mma_tf32(float c[4], const unsigned a[4], const unsigned b[2]) {
    asm volatile(
        "mma.sync.aligned.m16n8k8.row.col.f32.tf32.tf32.f32 "
        "{%0,%1,%2,%3}, {%4,%5,%6,%7}, {%8,%9}, {%0,%1,%2,%3};"
        : "+f"(c[0]), "+f"(c[1]), "+f"(c[2]), "+f"(c[3])
        : "r"(a[0]), "r"(a[1]), "r"(a[2]), "r"(a[3]), "r"(b[0]), "r"(b[1]));
}

__device__ __forceinline__ void cp16(void* smem_dst, const void* gsrc) {
    unsigned s = (unsigned)__cvta_generic_to_shared(smem_dst);
    asm volatile("cp.async.cg.shared.global [%0], [%1], 16;\n" :: "r"(s), "l"(gsrc));
}
#define CP_COMMIT() asm volatile("cp.async.commit_group;\n" ::: "memory")
#define CP_WAIT(N)  asm volatile("cp.async.wait_group %0;\n" :: "n"(N) : "memory")

// ---------------- pre-round inputs to tf32 ----------------
// x (4M), w_o (1M), w_dk/w_dv/w_uk/w_uv (128K each). Total 5,767,168 = 22528*256.
__global__ void round_inputs(const float* __restrict__ x,  const float* __restrict__ wo,
                             const float* __restrict__ wdk, const float* __restrict__ wdv,
                             const float* __restrict__ wuk, const float* __restrict__ wuv,
                             float* __restrict__ xr,  float* __restrict__ wor,
                             float* __restrict__ wdkr, float* __restrict__ wdvr,
                             float* __restrict__ wukr, float* __restrict__ wuvr) {
    int idx = blockIdx.x * blockDim.x + threadIdx.x;
    if (idx < BT * Dc) { xr[idx] = roundtf(x[idx]); return; }
    int i2 = idx - BT * Dc;
    if (i2 < Dc * Dc) { wor[i2] = roundtf(wo[i2]); return; }
    int i3 = i2 - Dc * Dc;
    int which = i3 >> 17;          // 0..3, 131072 each
    int off   = i3 & 131071;
    if      (which == 0) wdkr[off] = roundtf(wdk[off]);
    else if (which == 1) wdvr[off] = roundtf(wdv[off]);
    else if (which == 2) wukr[off] = roundtf(wuk[off]);
    else                 wuvr[off] = roundtf(wuv[off]);
}

// ---------------- tf32 tensor-core GEMM (inputs pre-rounded) ----------------
// BM=128, BN=128, BK=16, 256 threads, warp tile 32x64. 3-stage cp.async pipeline.
// z-dim selects between two fused problems.
#define GA_PAD 20
#define GB_PAD 136
#define G_STAGE_FLOATS (128 * GA_PAD + 16 * GB_PAD)   // 4736 floats
#define G_SMEM_BYTES   (3 * G_STAGE_FLOATS * 4)       // 56832 B

template<bool ROUND_OUT>
__global__ __launch_bounds__(256) void mma_gemm(
        const float* __restrict__ A0, const float* __restrict__ B0,
        const float* __restrict__ bi0, float* __restrict__ C0,
        const float* __restrict__ A1, const float* __restrict__ B1,
        const float* __restrict__ bi1, float* __restrict__ C1,
        int M, int N, int K) {
    const float* A    = blockIdx.z ? A1 : A0;
    const float* Bm   = blockIdx.z ? B1 : B0;
    const float* bias = blockIdx.z ? bi1 : bi0;
    float*       C    = blockIdx.z ? C1 : C0;

    extern __shared__ float gsm[];

    const int tid  = threadIdx.x;
    const int lane = tid & 31;
    const int wid  = tid >> 5;
    const int wm   = wid & 3;
    const int wn   = wid >> 2;
    const int g    = lane >> 2;
    const int qq   = lane & 3;

    const int row0 = blockIdx.y * 128;
    const int col0 = blockIdx.x * 128;
    const int nst  = K / 16;

    // per-thread load coords (2 chunks A, 2 chunks B per stage)
    const int a_row0 = tid >> 2,      a_c4 = tid & 3;         // i = tid
    const int a_row1 = (tid + 256) >> 2, a_c41 = (tid + 256) & 3;
    const int b_kr0 = tid >> 5,       b_n4 = tid & 31;
    const int b_kr1 = (tid + 256) >> 5, b_n41 = (tid + 256) & 31;

    auto issue = [&](int ks) {
        float* As = gsm + (ks % 3) * G_STAGE_FLOATS;
        float* Bs = As + 128 * GA_PAD;
        int k0 = ks * 16;
        cp16(As + a_row0 * GA_PAD + 4 * a_c4,  A + (long)(row0 + a_row0) * K + k0 + 4 * a_c4);
        cp16(As + a_row1 * GA_PAD + 4 * a_c41, A + (long)(row0 + a_row1) * K + k0 + 4 * a_c41);
        cp16(Bs + b_kr0 * GB_PAD + 4 * b_n4,  Bm + (long)(k0 + b_kr0) * N + col0 + 4 * b_n4);
        cp16(Bs + b_kr1 * GB_PAD + 4 * b_n41, Bm + (long)(k0 + b_kr1) * N + col0 + 4 * b_n41);
    };

    float acc[2][8][4];
    #pragma unroll
    for (int mi = 0; mi < 2; mi++)
        #pragma unroll
        for (int j = 0; j < 8; j++)
            #pragma unroll
            for (int e = 0; e < 4; e++) acc[mi][j][e] = 0.0f;

    issue(0); CP_COMMIT();
    issue(1); CP_COMMIT();

    for (int ks = 0; ks < nst; ks++) {
        CP_WAIT(1);
        __syncthreads();
        if (ks + 2 < nst) issue(ks + 2);
        CP_COMMIT();

        const unsigned* Asu = (const unsigned*)(gsm + (ks % 3) * G_STAGE_FLOATS);
        const unsigned* Bsu = Asu + 128 * GA_PAD;

        #pragma unroll
        for (int kk = 0; kk < 2; kk++) {
            unsigned a[2][4];
            #pragma unroll
            for (int mi = 0; mi < 2; mi++) {
                int m = 32 * wm + 16 * mi;
                a[mi][0] = Asu[(m + g    ) * GA_PAD + 8 * kk + qq];
                a[mi][1] = Asu[(m + g + 8) * GA_PAD + 8 * kk + qq];
                a[mi][2] = Asu[(m + g    ) * GA_PAD + 8 * kk + qq + 4];
                a[mi][3] = Asu[(m + g + 8) * GA_PAD + 8 * kk + qq + 4];
            }
            #pragma unroll
            for (int j = 0; j < 8; j++) {
                unsigned b[2];
                b[0] = Bsu[(8 * kk + qq    ) * GB_PAD + 64 * wn + 8 * j + g];
                b[1] = Bsu[(8 * kk + qq + 4) * GB_PAD + 64 * wn + 8 * j + g];
                mma_tf32(acc[0][j], a[0], b);
                mma_tf32(acc[1][j], a[1], b);
            }
        }
        __syncthreads();
    }

    #pragma unroll
    for (int mi = 0; mi < 2; mi++) {
        int row = row0 + 32 * wm + 16 * mi + g;
        #pragma unroll
        for (int j = 0; j < 8; j++) {
            int col = col0 + 64 * wn + 8 * j + 2 * qq;
            float b0 = bias[col], b1 = bias[col + 1];
            float v00 = acc[mi][j][0] + b0, v01 = acc[mi][j][1] + b1;
            float v10 = acc[mi][j][2] + b0, v11 = acc[mi][j][3] + b1;
            if (ROUND_OUT) {
                v00 = roundtf(v00); v01 = roundtf(v01);
                v10 = roundtf(v10); v11 = roundtf(v11);
            }
            *(float2*)&C[(long)row * N + col]       = make_float2(v00, v01);
            *(float2*)&C[(long)(row + 8) * N + col] = make_float2(v10, v11);
        }
    }
}

// ---------------- RoPE + head split (outputs rounded to tf32) ----------------
__global__ void prepare_qkv(const float* __restrict__ x,
                            const float* __restrict__ kf,
                            const float* __restrict__ vf,
                            float* __restrict__ qh,
                            float* __restrict__ kh,
                            float* __restrict__ vh) {
    int idx = blockIdx.x * blockDim.x + threadIdx.x;
    int d = idx & 63;
    int t = (idx >> 6) & 2047;
    int h = (idx >> 17) & 15;
    int b = idx >> 21;
    long src = ((long)(b * Tc + t)) * Dc + h * DHc + d;

    int i2 = d & 31;
    float inv_freq = powf(10000.0f, -(float)i2 / 32.0f);
    float ang = (float)t * inv_freq;
    float sv, cv;
    sincosf(ang, &sv, &cv);

    float xv = x[src];
    float xr = (d < 32) ? -x[src + 32] : x[src - 32];
    qh[idx] = roundtf(xv * cv + xr * sv);

    float kv = kf[src];
    float kr = (d < 32) ? -kf[src + 32] : kf[src - 32];
    kh[idx] = roundtf(kv * cv + kr * sv);

    vh[idx] = roundtf(vf[src]);
}

// ---------------- flash attention, tf32 mma, 3-stage cp.async ----------------
// 256 threads (8 warps), 128 q-rows per CTA (16/warp), 64-key tiles.
// Q in registers; P redistributed C-frag -> A-frag via shuffles (no smem).
#define KS_STRIDE 68
#define VS_STRIDE 72
#define ATT_BUF_FLOATS (64 * KS_STRIDE + 64 * VS_STRIDE)   // 8960
#define ATT_SMEM_BYTES (3 * ATT_BUF_FLOATS * 4)            // 107520

__global__ __launch_bounds__(256, 2) void attn_kernel(
        const float* __restrict__ qh,
        const float* __restrict__ kh,
        const float* __restrict__ vh,
        float* __restrict__ out) {
    extern __shared__ float sm[];

    const int tid  = threadIdx.x;
    const int lane = tid & 31;
    const int w    = tid >> 5;
    const int g    = lane >> 2;
    const int qq   = lane & 3;

    const int bh = blockIdx.y;
    const int b  = bh >> 4;
    const int h  = bh & 15;
    const int t0 = blockIdx.x * 128;

    const float* qp = qh + ((long)bh * Tc + t0) * DHc;
    const float* kp = kh + (long)bh * Tc * DHc;
    const float* vp = vh + (long)bh * Tc * DHc;

    // Q fragments (already tf32-rounded bits)
    const unsigned* qpu = (const unsigned*)qp;
    unsigned qa[8][4];
    #pragma unroll
    for (int kk = 0; kk < 8; kk++) {
        qa[kk][0] = qpu[(16 * w + g    ) * 64 + 8 * kk + qq];
        qa[kk][1] = qpu[(16 * w + g + 8) * 64 + 8 * kk + qq];
        qa[kk][2] = qpu[(16 * w + g    ) * 64 + 8 * kk + qq + 4];
        qa[kk][3] = qpu[(16 * w + g + 8) * 64 + 8 * kk + qq + 4];
    }

    // per-thread load coords: 4 K-chunks + 4 V-chunks per tile
    auto issue = [&](int tile) {
        float* Kd = sm + (tile % 3) * ATT_BUF_FLOATS;
        float* Vd = Kd + 64 * KS_STRIDE;
        int kt = tile * 64;
        #pragma unroll
        for (int i = tid; i < 1024; i += 256) {
            int n = i >> 4, d4 = i & 15;
            cp16(Kd + n * KS_STRIDE + 4 * d4, kp + (long)(kt + n) * 64 + 4 * d4);
            cp16(Vd + n * VS_STRIDE + 4 * d4, vp + (long)(kt + n) * 64 + 4 * d4);
        }
    };

    float o[8][4];
    #pragma unroll
    for (int j = 0; j < 8; j++)
        #pragma unroll
        for (int e = 0; e < 4; e++) o[j][e] = 0.0f;
    float m_i[2] = {-1e30f, -1e30f};
    float l_i[2] = {0.0f, 0.0f};

    issue(0); CP_COMMIT();
    issue(1); CP_COMMIT();

    for (int it = 0; it < 32; it++) {
        CP_WAIT(1);
        __syncthreads();
        if (it + 2 < 32) issue(it + 2);
        CP_COMMIT();

        const unsigned* Ku = (const unsigned*)(sm + (it % 3) * ATT_BUF_FLOATS);
        const unsigned* Vu = Ku + 64 * KS_STRIDE;

        // S = Q @ K^T
        float s[8][4];
        #pragma unroll
        for (int j = 0; j < 8; j++)
            #pragma unroll
            for (int e = 0; e < 4; e++) s[j][e] = 0.0f;
        #pragma unroll
        for (int kk = 0; kk < 8; kk++) {
            #pragma unroll
            for (int j = 0; j < 8; j++) {
                unsigned bfr[2];
                bfr[0] = Ku[(8 * j + g) * KS_STRIDE + 8 * kk + qq];
                bfr[1] = Ku[(8 * j + g) * KS_STRIDE + 8 * kk + qq + 4];
                mma_tf32(s[j], qa[kk], bfr);
            }
        }

        // online softmax (p values kept in s)
        #pragma unroll
        for (int hh = 0; hh < 2; hh++) {
            float mt = -1e30f;
            #pragma unroll
            for (int j = 0; j < 8; j++) {
                s[j][2 * hh]     *= 0.125f;
                s[j][2 * hh + 1] *= 0.125f;
                mt = fmaxf(mt, fmaxf(s[j][2 * hh], s[j][2 * hh + 1]));
            }
            mt = fmaxf(mt, __shfl_xor_sync(0xffffffffu, mt, 1));
            mt = fmaxf(mt, __shfl_xor_sync(0xffffffffu, mt, 2));

            float mnew = fmaxf(m_i[hh], mt);
            float corr = __expf(m_i[hh] - mnew);
            float lsum = 0.0f;
            #pragma unroll
            for (int j = 0; j < 8; j++) {
                float p0 = __expf(s[j][2 * hh]     - mnew);
                float p1 = __expf(s[j][2 * hh + 1] - mnew);
                s[j][2 * hh]     = p0;
                s[j][2 * hh + 1] = p1;
                lsum += p0 + p1;
            }
            lsum += __shfl_xor_sync(0xffffffffu, lsum, 1);
            lsum += __shfl_xor_sync(0xffffffffu, lsum, 2);

            l_i[hh] = l_i[hh] * corr + lsum;
            m_i[hh] = mnew;
            #pragma unroll
            for (int j = 0; j < 8; j++) {
                o[j][2 * hh]     *= corr;
                o[j][2 * hh + 1] *= corr;
            }
        }

        // O += P @ V  (P redistributed C-frag -> A-frag via shuffles)
        #pragma unroll
        for (int kk = 0; kk < 8; kk++) {
            int src = (lane & ~3) | (qq >> 1);
            float a0 = __shfl_sync(0xffffffffu, s[kk][0], src);
            float a1 = __shfl_sync(0xffffffffu, s[kk][1], src);
            float a2 = __shfl_sync(0xffffffffu, s[kk][2], src);
            float a3 = __shfl_sync(0xffffffffu, s[kk][3], src);
            float b0 = __shfl_sync(0xffffffffu, s[kk][0], src + 2);
            float b1 = __shfl_sync(0xffffffffu, s[kk][1], src + 2);
            float b2 = __shfl_sync(0xffffffffu, s[kk][2], src + 2);
            float b3 = __shfl_sync(0xffffffffu, s[kk][3], src + 2);
            bool odd = qq & 1;
            unsigned pa[4];
            pa[0] = f2tf32(odd ? a1 : a0);
            pa[1] = f2tf32(odd ? a3 : a2);
            pa[2] = f2tf32(odd ? b1 : b0);
            pa[3] = f2tf32(odd ? b3 : b2);
            #pragma unroll
            for (int j = 0; j < 8; j++) {
                unsigned bfr[2];
                bfr[0] = Vu[(8 * kk + qq    ) * VS_STRIDE + 8 * j + g];
                bfr[1] = Vu[(8 * kk + qq + 4) * VS_STRIDE + 8 * j + g];
                mma_tf32(o[j], pa, bfr);
            }
        }
    }

    // epilogue: normalize, round (feeds out-proj), write to [B,T,D]
    float inv0 = 1.0f / l_i[0];
    float inv1 = 1.0f / l_i[1];
    int t_r0 = t0 + 16 * w + g;
    long base0 = ((long)b * Tc + t_r0) * Dc + h * DHc;
    long base1 = ((long)b * Tc + t_r0 + 8) * Dc + h * DHc;
    #pragma unroll
    for (int j = 0; j < 8; j++) {
        int col = 8 * j + 2 * qq;
        *(float2*)&out[base0 + col] =
            make_float2(roundtf(o[j][0] * inv0), roundtf(o[j][1] * inv0));
        *(float2*)&out[base1 + col] =
            make_float2(roundtf(o[j][2] * inv1), roundtf(o[j][3] * inv1));
    }
}

// ---------------- launch ----------------
extern "C" void kernel_launch(void* const* d_in, const int* in_sizes, int n_in,
                              void* d_out, int out_size) {
    const float* x    = (const float*)d_in[0];
    const float* w_dk = (const float*)d_in[1];
    const float* b_dk = (const float*)d_in[2];
    const float* w_dv = (const float*)d_in[3];
    const float* b_dv = (const float*)d_in[4];
    const float* w_uk = (const float*)d_in[5];
    const float* b_uk = (const float*)d_in[6];
    const float* w_uv = (const float*)d_in[7];
    const float* b_uv = (const float*)d_in[8];
    const float* w_o  = (const float*)d_in[9];
    const float* b_o  = (const float*)d_in[10];
    float* out = (float*)d_out;

    float *ck, *cv, *kf, *vf, *qv, *kh, *vh, *ao;
    float *xr, *wor, *wdkr, *wdvr, *wukr, *wuvr;
    cudaGetSymbolAddress((void**)&ck, g_ck);
    cudaGetSymbolAddress((void**)&cv, g_cv);
    cudaGetSymbolAddress((void**)&kf, g_kf);
    cudaGetSymbolAddress((void**)&vf, g_vf);
    cudaGetSymbolAddress((void**)&qv, g_q);
    cudaGetSymbolAddress((void**)&kh, g_kh);
    cudaGetSymbolAddress((void**)&vh, g_vh);
    cudaGetSymbolAddress((void**)&ao, g_ao);
    cudaGetSymbolAddress((void**)&xr, g_xr);
    cudaGetSymbolAddress((void**)&wor, g_wor);
    cudaGetSymbolAddress((void**)&wdkr, g_wdkr);
    cudaGetSymbolAddress((void**)&wdvr, g_wdvr);
    cudaGetSymbolAddress((void**)&wukr, g_wukr);
    cudaGetSymbolAddress((void**)&wuvr, g_wuvr);

    static int attrs_set = 0;
    if (!attrs_set) {
        cudaFuncSetAttribute(mma_gemm<true>,  cudaFuncAttributeMaxDynamicSharedMemorySize, G_SMEM_BYTES);
        cudaFuncSetAttribute(mma_gemm<false>, cudaFuncAttributeMaxDynamicSharedMemorySize, G_SMEM_BYTES);
        cudaFuncSetAttribute(attn_kernel, cudaFuncAttributeMaxDynamicSharedMemorySize, ATT_SMEM_BYTES);
        attrs_set = 1;
    }

    dim3 blk(256);

    // pre-round x + all weights to tf32
    round_inputs<<<22528, 256>>>(x, w_o, w_dk, w_dv, w_uk, w_uv,
                                 xr, wor, wdkr, wdvr, wukr, wuvr);

    // down-projections (fused via z): (BT x 1024) @ (1024 x 128) -> rounded ck/cv
    mma_gemm<true><<<dim3(Cc / 128, BT / 128, 2), blk, G_SMEM_BYTES>>>(
        xr, wdkr, b_dk, ck, xr, wdvr, b_dv, cv, BT, Cc, Dc);

    // up-projections (fused via z): (BT x 128) @ (128 x 1024) -> fp32 kf/vf
    mma_gemm<false><<<dim3(Dc / 128, BT / 128, 2), blk, G_SMEM_BYTES>>>(
        ck, wukr, b_uk, kf, cv, wuvr, b_uv, vf, BT, Dc, Cc);

    // RoPE + head split (rounds q/kh/vh)
    prepare_qkv<<<(BT * Dc) / 256, 256>>>(x, kf, vf, qv, kh, vh);

    // attention (rounds ao)
    attn_kernel<<<dim3(Tc / 128, Bc * Hc), blk, ATT_SMEM_BYTES>>>(qv, kh, vh, ao);

    // output projection: (BT x 1024) @ (1024 x 1024)
    mma_gemm<false><<<dim3(Dc / 128, BT / 128, 1), blk, G_SMEM_BYTES>>>(
        ao, wor, b_o, out, ao, wor, b_o, out, BT, Dc, Dc);
}

// round 5
// speedup vs baseline: 6.4090x; 1.7567x over previous
#include <cuda_runtime.h>
#include <cuda_fp16.h>
#include <math.h>
#include <stdint.h>

// Problem constants
#define Bc   2
#define Tc   2048
#define Dc   1024
#define Hc   16
#define DHc  64
#define Cc   128
#define BT   4096   // B*T

// ---------------- scratch (no allocations allowed) ----------------
__device__ __half g_xh  [BT * Dc];      // x in fp16
__device__ __half g_wdkT[Cc * Dc];      // w_dk^T fp16 [C][D]
__device__ __half g_wdvT[Cc * Dc];
__device__ __half g_wukT[Dc * Cc];      // w_uk^T fp16 [D][C]
__device__ __half g_wuvT[Dc * Cc];
__device__ __half g_woT [Dc * Dc];      // w_o^T fp16
__device__ __half g_ck  [BT * Cc];      // fp16
__device__ __half g_cv  [BT * Cc];
__device__ float  g_kf  [BT * Dc];      // fp32 pre-rope
__device__ float  g_vf  [BT * Dc];
__device__ __half g_qh  [BT * Dc];      // [B,H,T,DH] fp16
__device__ __half g_kh  [BT * Dc];      // [B,H,T,DH] fp16
__device__ __half g_vt  [BT * Dc];      // [B,H,DH,T] fp16 (V transposed)
__device__ __half g_ao  [BT * Dc];      // attention out [B,T,D] fp16

// ---------------- helpers ----------------
__device__ __forceinline__ void mma_f16(float c[4], const unsigned a[4], const unsigned b[2]) {
    asm volatile(
        "mma.sync.aligned.m16n8k16.row.col.f32.f16.f16.f32 "
        "{%0,%1,%2,%3}, {%4,%5,%6,%7}, {%8,%9}, {%0,%1,%2,%3};"
        : "+f"(c[0]), "+f"(c[1]), "+f"(c[2]), "+f"(c[3])
        : "r"(a[0]), "r"(a[1]), "r"(a[2]), "r"(a[3]), "r"(b[0]), "r"(b[1]));
}

__device__ __forceinline__ void cp16(void* smem_dst, const void* gsrc) {
    unsigned s = (unsigned)__cvta_generic_to_shared(smem_dst);
    asm volatile("cp.async.cg.shared.global [%0], [%1], 16;\n" :: "r"(s), "l"(gsrc));
}
#define CP_COMMIT() asm volatile("cp.async.commit_group;\n" ::: "memory")
#define CP_WAIT(N)  asm volatile("cp.async.wait_group %0;\n" :: "n"(N) : "memory")

__device__ __forceinline__ unsigned pack_h2(float lo, float hi) {
    __half2 h = __floats2half2_rn(lo, hi);
    return *(unsigned*)&h;
}

// ---------------- input conversion ----------------
__global__ void convert_x(const float* __restrict__ x, __half* __restrict__ xh) {
    int idx = blockIdx.x * blockDim.x + threadIdx.x;
    xh[idx] = __float2half(x[idx]);
}

// transpose + convert: src fp32 [R][Cn] -> dst fp16 [Cn][R]
__global__ void transpose_cvt(const float* __restrict__ src, __half* __restrict__ dst,
                              int R, int Cn) {
    __shared__ float tile[32][33];
    int c0 = blockIdx.x * 32, r0 = blockIdx.y * 32;
    int tx = threadIdx.x, ty = threadIdx.y;   // 32 x 8
    #pragma unroll
    for (int i = 0; i < 4; i++)
        tile[ty + 8 * i][tx] = src[(long)(r0 + ty + 8 * i) * Cn + c0 + tx];
    __syncthreads();
    #pragma unroll
    for (int i = 0; i < 4; i++)
        dst[(long)(c0 + ty + 8 * i) * R + r0 + tx] = __float2half(tile[tx][ty + 8 * i]);
}

// ---------------- fp16 tensor-core GEMM ----------------
// C = A @ B + bias, with B supplied TRANSPOSED ([N][K] fp16).
// BM=BN=128, BK=32, 256 threads, warp tile 32x64, 3-stage cp.async pipeline.
// z-dim selects between two fused problems.
#define GA_ST 40   // halves per A row (32 + 8 pad)
#define GB_ST 40
#define G_STAGE_HALVES (128 * GA_ST + 128 * GB_ST)    // 10240
#define G_SMEM_BYTES   (3 * G_STAGE_HALVES * 2)       // 61440

template<typename OutT>
__global__ __launch_bounds__(256) void mma_gemm(
        const __half* __restrict__ A0, const __half* __restrict__ Bt0,
        const float* __restrict__ bi0, OutT* __restrict__ C0,
        const __half* __restrict__ A1, const __half* __restrict__ Bt1,
        const float* __restrict__ bi1, OutT* __restrict__ C1,
        int M, int N, int K) {
    const __half* A    = blockIdx.z ? A1 : A0;
    const __half* Bt   = blockIdx.z ? Bt1 : Bt0;
    const float*  bias = blockIdx.z ? bi1 : bi0;
    OutT*         C    = blockIdx.z ? C1 : C0;

    extern __shared__ __half gsm[];

    const int tid  = threadIdx.x;
    const int lane = tid & 31;
    const int wid  = tid >> 5;
    const int wm   = wid & 3;
    const int wn   = wid >> 2;
    const int g    = lane >> 2;
    const int qq   = lane & 3;

    const int row0 = blockIdx.y * 128;
    const int col0 = blockIdx.x * 128;
    const int nst  = K / 32;

    auto issue = [&](int ks) {
        __half* As = gsm + (ks % 3) * G_STAGE_HALVES;
        __half* Bs = As + 128 * GA_ST;
        int k0 = ks * 32;
        #pragma unroll
        for (int i = tid; i < 512; i += 256) {
            int row = i >> 2, c = i & 3;
            cp16(As + row * GA_ST + 8 * c, A  + (long)(row0 + row) * K + k0 + 8 * c);
            cp16(Bs + row * GB_ST + 8 * c, Bt + (long)(col0 + row) * K + k0 + 8 * c);
        }
    };

    float acc[2][8][4];
    #pragma unroll
    for (int mi = 0; mi < 2; mi++)
        #pragma unroll
        for (int j = 0; j < 8; j++)
            #pragma unroll
            for (int e = 0; e < 4; e++) acc[mi][j][e] = 0.0f;

    issue(0); CP_COMMIT();
    issue(1); CP_COMMIT();

    for (int ks = 0; ks < nst; ks++) {
        CP_WAIT(1);
        __syncthreads();
        if (ks + 2 < nst) issue(ks + 2);
        CP_COMMIT();

        const __half* As = gsm + (ks % 3) * G_STAGE_HALVES;
        const __half* Bs = As + 128 * GA_ST;

        #pragma unroll
        for (int kk = 0; kk < 2; kk++) {
            unsigned a[2][4];
            #pragma unroll
            for (int mi = 0; mi < 2; mi++) {
                int m = 32 * wm + 16 * mi;
                a[mi][0] = *(const unsigned*)&As[(m + g    ) * GA_ST + 16 * kk + 2 * qq];
                a[mi][1] = *(const unsigned*)&As[(m + g + 8) * GA_ST + 16 * kk + 2 * qq];
                a[mi][2] = *(const unsigned*)&As[(m + g    ) * GA_ST + 16 * kk + 2 * qq + 8];
                a[mi][3] = *(const unsigned*)&As[(m + g + 8) * GA_ST + 16 * kk + 2 * qq + 8];
            }
            #pragma unroll
            for (int j = 0; j < 8; j++) {
                const __half* bb = &Bs[(64 * wn + 8 * j + g) * GB_ST + 16 * kk + 2 * qq];
                unsigned b[2];
                b[0] = *(const unsigned*)(bb);
                b[1] = *(const unsigned*)(bb + 8);
                mma_f16(acc[0][j], a[0], b);
                mma_f16(acc[1][j], a[1], b);
            }
        }
        __syncthreads();
    }

    #pragma unroll
    for (int mi = 0; mi < 2; mi++) {
        int row = row0 + 32 * wm + 16 * mi + g;
        #pragma unroll
        for (int j = 0; j < 8; j++) {
            int col = col0 + 64 * wn + 8 * j + 2 * qq;
            float b0 = bias[col], b1 = bias[col + 1];
            float v00 = acc[mi][j][0] + b0, v01 = acc[mi][j][1] + b1;
            float v10 = acc[mi][j][2] + b0, v11 = acc[mi][j][3] + b1;
            if (sizeof(OutT) == 2) {
                __half2* p0 = (__half2*)&C[(long)row * N + col];
                __half2* p1 = (__half2*)&C[(long)(row + 8) * N + col];
                *p0 = __floats2half2_rn(v00, v01);
                *p1 = __floats2half2_rn(v10, v11);
            } else {
                *(float2*)&C[(long)row * N + col]       = make_float2(v00, v01);
                *(float2*)&C[(long)(row + 8) * N + col] = make_float2(v10, v11);
            }
        }
    }
}

// ---------------- RoPE + head split + V transpose (fp16 outputs) ----------------
// Block handles 64 t-rows x 64 d for one (b,h). qh/kh: [B,H,T,DH]; vt: [B,H,DH,T].
#define VS_T_ST 68
__global__ void prepare_qkv(const float* __restrict__ x,
                            const float* __restrict__ kf,
                            const float* __restrict__ vf,
                            __half* __restrict__ qh,
                            __half* __restrict__ kh,
                            __half* __restrict__ vt) {
    __shared__ __half vs[64][VS_T_ST];
    const int tid = threadIdx.x;
    const int t0  = blockIdx.x * 64;
    const int bh  = blockIdx.y;
    const int b   = bh >> 4;
    const int h   = bh & 15;

    #pragma unroll
    for (int it = 0; it < 16; it++) {
        int idx = it * 256 + tid;
        int tl = idx >> 6, d = idx & 63;
        int t = t0 + tl;
        long src = ((long)(b * Tc + t)) * Dc + h * DHc + d;

        int i2 = d & 31;
        float inv_freq = powf(10000.0f, -(float)i2 / 32.0f);
        float ang = (float)t * inv_freq;
        float sv, cv;
        sincosf(ang, &sv, &cv);

        float xv = x[src];
        float xr = (d < 32) ? -x[src + 32] : x[src - 32];
        long dst = ((long)bh * Tc + t) * DHc + d;
        qh[dst] = __float2half(xv * cv + xr * sv);

        float kv = kf[src];
        float kr = (d < 32) ? -kf[src + 32] : kf[src - 32];
        kh[dst] = __float2half(kv * cv + kr * sv);

        vs[d][tl] = __float2half(vf[src]);
    }
    __syncthreads();
    #pragma unroll
    for (int it = 0; it < 16; it++) {
        int idx = it * 256 + tid;
        int d = idx >> 6, tl = idx & 63;
        vt[((long)bh * DHc + d) * Tc + t0 + tl] = vs[d][tl];
    }
}

// ---------------- flash attention, fp16 mma ----------------
// 256 threads (8 warps), 128 q-rows per CTA (16/warp), 64-key tiles,
// 3-stage cp.async. K smem [key][d], V smem transposed [d][key].
// P goes C-frag -> A-frag with pure register repacking (no shuffles).
#define KS_ST 72   // halves
#define VT_ST 72
#define ATT_BUF_HALVES (64 * KS_ST + 64 * VT_ST)     // 9216
#define ATT_SMEM_BYTES (3 * ATT_BUF_HALVES * 2)      // 55296

__global__ __launch_bounds__(256, 2) void attn_kernel(
        const __half* __restrict__ qh,
        const __half* __restrict__ kh,
        const __half* __restrict__ vt,
        __half* __restrict__ out) {
    extern __shared__ __half sma[];

    const int tid  = threadIdx.x;
    const int lane = tid & 31;
    const int w    = tid >> 5;
    const int g    = lane >> 2;
    const int qq   = lane & 3;

    const int bh = blockIdx.y;
    const int b  = bh >> 4;
    const int h  = bh & 15;
    const int t0 = blockIdx.x * 128;

    const __half* qp = qh + ((long)bh * Tc + t0) * DHc;
    const __half* kp = kh + (long)bh * Tc * DHc;
    const __half* vp = vt + (long)bh * DHc * Tc;

    // Q fragments: 4 k16-steps, each 4 half2 regs
    unsigned qa[4][4];
    #pragma unroll
    for (int kk = 0; kk < 4; kk++) {
        qa[kk][0] = *(const unsigned*)&qp[(16 * w + g    ) * 64 + 16 * kk + 2 * qq];
        qa[kk][1] = *(const unsigned*)&qp[(16 * w + g + 8) * 64 + 16 * kk + 2 * qq];
        qa[kk][2] = *(const unsigned*)&qp[(16 * w + g    ) * 64 + 16 * kk + 2 * qq + 8];
        qa[kk][3] = *(const unsigned*)&qp[(16 * w + g + 8) * 64 + 16 * kk + 2 * qq + 8];
    }

    auto issue = [&](int tile) {
        __half* Kd = sma + (tile % 3) * ATT_BUF_HALVES;
        __half* Vd = Kd + 64 * KS_ST;
        int kt = tile * 64;
        #pragma unroll
        for (int i = tid; i < 512; i += 256) {
            int r = i >> 3, c = i & 7;
            cp16(Kd + r * KS_ST + 8 * c, kp + (long)(kt + r) * 64 + 8 * c);
            cp16(Vd + r * VT_ST + 8 * c, vp + (long)r * Tc + kt + 8 * c);
        }
    };

    float o[8][4];
    #pragma unroll
    for (int j = 0; j < 8; j++)
        #pragma unroll
        for (int e = 0; e < 4; e++) o[j][e] = 0.0f;
    float m_i[2] = {-1e30f, -1e30f};
    float l_i[2] = {0.0f, 0.0f};

    issue(0); CP_COMMIT();
    issue(1); CP_COMMIT();

    for (int it = 0; it < 32; it++) {
        CP_WAIT(1);
        __syncthreads();
        if (it + 2 < 32) issue(it + 2);
        CP_COMMIT();

        const __half* Ku = sma + (it % 3) * ATT_BUF_HALVES;
        const __half* Vu = Ku + 64 * KS_ST;

        // S = Q @ K^T   (16x64 per warp; 4 k16-steps over DH)
        float s[8][4];
        #pragma unroll
        for (int j = 0; j < 8; j++)
            #pragma unroll
            for (int e = 0; e < 4; e++) s[j][e] = 0.0f;
        #pragma unroll
        for (int kk = 0; kk < 4; kk++) {
            #pragma unroll
            for (int j = 0; j < 8; j++) {
                const __half* bb = &Ku[(8 * j + g) * KS_ST + 16 * kk + 2 * qq];
                unsigned bfr[2];
                bfr[0] = *(const unsigned*)(bb);
                bfr[1] = *(const unsigned*)(bb + 8);
                mma_f16(s[j], qa[kk], bfr);
            }
        }

        // online softmax (P kept in s)
        #pragma unroll
        for (int hh = 0; hh < 2; hh++) {
            float mt = -1e30f;
            #pragma unroll
            for (int j = 0; j < 8; j++) {
                s[j][2 * hh]     *= 0.125f;
                s[j][2 * hh + 1] *= 0.125f;
                mt = fmaxf(mt, fmaxf(s[j][2 * hh], s[j][2 * hh + 1]));
            }
            mt = fmaxf(mt, __shfl_xor_sync(0xffffffffu, mt, 1));
            mt = fmaxf(mt, __shfl_xor_sync(0xffffffffu, mt, 2));

            float mnew = fmaxf(m_i[hh], mt);
            float corr = __expf(m_i[hh] - mnew);
            float lsum = 0.0f;
            #pragma unroll
            for (int j = 0; j < 8; j++) {
                float p0 = __expf(s[j][2 * hh]     - mnew);
                float p1 = __expf(s[j][2 * hh + 1] - mnew);
                s[j][2 * hh]     = p0;
                s[j][2 * hh + 1] = p1;
                lsum += p0 + p1;
            }
            lsum += __shfl_xor_sync(0xffffffffu, lsum, 1);
            lsum += __shfl_xor_sync(0xffffffffu, lsum, 2);

            l_i[hh] = l_i[hh] * corr + lsum;
            m_i[hh] = mnew;
            #pragma unroll
            for (int j = 0; j < 8; j++) {
                o[j][2 * hh]     *= corr;
                o[j][2 * hh + 1] *= corr;
            }
        }

        // O += P @ V : C-frag of S maps directly to fp16 A-frag (register repack)
        #pragma unroll
        for (int kk = 0; kk < 4; kk++) {
            unsigned pa[4];
            pa[0] = pack_h2(s[2 * kk][0],     s[2 * kk][1]);
            pa[1] = pack_h2(s[2 * kk][2],     s[2 * kk][3]);
            pa[2] = pack_h2(s[2 * kk + 1][0], s[2 * kk + 1][1]);
            pa[3] = pack_h2(s[2 * kk + 1][2], s[2 * kk + 1][3]);
            #pragma unroll
            for (int j = 0; j < 8; j++) {
                const __half* bb = &Vu[(8 * j + g) * VT_ST + 16 * kk + 2 * qq];
                unsigned bfr[2];
                bfr[0] = *(const unsigned*)(bb);
                bfr[1] = *(const unsigned*)(bb + 8);
                mma_f16(o[j], pa, bfr);
            }
        }
    }

    // epilogue: normalize, write fp16 to [B,T,D]
    float inv0 = 1.0f / l_i[0];
    float inv1 = 1.0f / l_i[1];
    int t_r0 = t0 + 16 * w + g;
    long base0 = ((long)b * Tc + t_r0) * Dc + h * DHc;
    long base1 = ((long)b * Tc + t_r0 + 8) * Dc + h * DHc;
    #pragma unroll
    for (int j = 0; j < 8; j++) {
        int col = 8 * j + 2 * qq;
        *(__half2*)&out[base0 + col] = __floats2half2_rn(o[j][0] * inv0, o[j][1] * inv0);
        *(__half2*)&out[base1 + col] = __floats2half2_rn(o[j][2] * inv1, o[j][3] * inv1);
    }
}

// ---------------- launch ----------------
extern "C" void kernel_launch(void* const* d_in, const int* in_sizes, int n_in,
                              void* d_out, int out_size) {
    const float* x    = (const float*)d_in[0];
    const float* w_dk = (const float*)d_in[1];
    const float* b_dk = (const float*)d_in[2];
    const float* w_dv = (const float*)d_in[3];
    const float* b_dv = (const float*)d_in[4];
    const float* w_uk = (const float*)d_in[5];
    const float* b_uk = (const float*)d_in[6];
    const float* w_uv = (const float*)d_in[7];
    const float* b_uv = (const float*)d_in[8];
    const float* w_o  = (const float*)d_in[9];
    const float* b_o  = (const float*)d_in[10];
    float* out = (float*)d_out;

    __half *xh, *wdkT, *wdvT, *wukT, *wuvT, *woT, *ck, *cv, *qh, *kh, *vt, *ao;
    float *kf, *vf;
    cudaGetSymbolAddress((void**)&xh,   g_xh);
    cudaGetSymbolAddress((void**)&wdkT, g_wdkT);
    cudaGetSymbolAddress((void**)&wdvT, g_wdvT);
    cudaGetSymbolAddress((void**)&wukT, g_wukT);
    cudaGetSymbolAddress((void**)&wuvT, g_wuvT);
    cudaGetSymbolAddress((void**)&woT,  g_woT);
    cudaGetSymbolAddress((void**)&ck,   g_ck);
    cudaGetSymbolAddress((void**)&cv,   g_cv);
    cudaGetSymbolAddress((void**)&kf,   g_kf);
    cudaGetSymbolAddress((void**)&vf,   g_vf);
    cudaGetSymbolAddress((void**)&qh,   g_qh);
    cudaGetSymbolAddress((void**)&kh,   g_kh);
    cudaGetSymbolAddress((void**)&vt,   g_vt);
    cudaGetSymbolAddress((void**)&ao,   g_ao);

    static int attrs_set = 0;
    if (!attrs_set) {
        cudaFuncSetAttribute(mma_gemm<__half>, cudaFuncAttributeMaxDynamicSharedMemorySize, G_SMEM_BYTES);
        cudaFuncSetAttribute(mma_gemm<float>,  cudaFuncAttributeMaxDynamicSharedMemorySize, G_SMEM_BYTES);
        cudaFuncSetAttribute(attn_kernel, cudaFuncAttributeMaxDynamicSharedMemorySize, ATT_SMEM_BYTES);
        attrs_set = 1;
    }

    dim3 blk(256);
    dim3 tblk(32, 8);

    // convert x to fp16; transpose+convert all weights
    convert_x<<<(BT * Dc) / 256, 256>>>(x, xh);
    transpose_cvt<<<dim3(Cc / 32, Dc / 32), tblk>>>(w_dk, wdkT, Dc, Cc);
    transpose_cvt<<<dim3(Cc / 32, Dc / 32), tblk>>>(w_dv, wdvT, Dc, Cc);
    transpose_cvt<<<dim3(Dc / 32, Cc / 32), tblk>>>(w_uk, wukT, Cc, Dc);
    transpose_cvt<<<dim3(Dc / 32, Cc / 32), tblk>>>(w_uv, wuvT, Cc, Dc);
    transpose_cvt<<<dim3(Dc / 32, Dc / 32), tblk>>>(w_o,  woT,  Dc, Dc);

    // down-projections (fused via z): (BT x 1024) @ (1024 x 128) -> fp16 ck/cv
    mma_gemm<__half><<<dim3(Cc / 128, BT / 128, 2), blk, G_SMEM_BYTES>>>(
        xh, wdkT, b_dk, ck, xh, wdvT, b_dv, cv, BT, Cc, Dc);

    // up-projections (fused via z): (BT x 128) @ (128 x 1024) -> fp32 kf/vf
    mma_gemm<float><<<dim3(Dc / 128, BT / 128, 2), blk, G_SMEM_BYTES>>>(
        ck, wukT, b_uk, kf, cv, wuvT, b_uv, vf, BT, Dc, Cc);

    // RoPE + head split + V transpose
    prepare_qkv<<<dim3(Tc / 64, Bc * Hc), blk>>>(x, kf, vf, qh, kh, vt);

    // attention
    attn_kernel<<<dim3(Tc / 128, Bc * Hc), blk, ATT_SMEM_BYTES>>>(qh, kh, vt, ao);

    // output projection: (BT x 1024) @ (1024 x 1024) -> fp32 out
    mma_gemm<float><<<dim3(Dc / 128, BT / 128, 1), blk, G_SMEM_BYTES>>>(
        ao, woT, b_o, out, ao, woT, b_o, out, BT, Dc, Dc);
}

// round 7
// speedup vs baseline: 7.1249x; 1.1117x over previous
#include <cuda_runtime.h>
#include <cuda_fp16.h>
#include <math.h>
#include <stdint.h>

// Problem constants
#define Bc   2
#define Tc   2048
#define Dc   1024
#define Hc   16
#define DHc  64
#define Cc   128
#define BT   4096   // B*T

// ---------------- scratch (no allocations allowed) ----------------
__device__ __half g_xh  [BT * Dc];      // x in fp16
__device__ __half g_wdkT[Cc * Dc];      // w_dk^T fp16 [C][D]
__device__ __half g_wdvT[Cc * Dc];
__device__ __half g_wukT[Dc * Cc];      // w_uk^T fp16 [D][C]
__device__ __half g_wuvT[Dc * Cc];
__device__ __half g_woT [Dc * Dc];      // w_o^T fp16
__device__ __half g_ck  [BT * Cc];      // fp16
__device__ __half g_cv  [BT * Cc];
__device__ __half g_kf  [BT * Dc];      // fp16 pre-rope
__device__ __half g_vf  [BT * Dc];
__device__ __half g_qh  [BT * Dc];      // [B,H,T,DH] fp16
__device__ __half g_kh  [BT * Dc];      // [B,H,T,DH] fp16
__device__ __half g_vt  [BT * Dc];      // [B,H,DH,T] fp16 (V transposed)
__device__ __half g_ao  [BT * Dc];      // attention out [B,T,D] fp16

// ---------------- helpers ----------------
__device__ __forceinline__ void mma_f16(float c[4], const unsigned a[4], const unsigned b[2]) {
    asm volatile(
        "mma.sync.aligned.m16n8k16.row.col.f32.f16.f16.f32 "
        "{%0,%1,%2,%3}, {%4,%5,%6,%7}, {%8,%9}, {%0,%1,%2,%3};"
        : "+f"(c[0]), "+f"(c[1]), "+f"(c[2]), "+f"(c[3])
        : "r"(a[0]), "r"(a[1]), "r"(a[2]), "r"(a[3]), "r"(b[0]), "r"(b[1]));
}

__device__ __forceinline__ void cp16(void* smem_dst, const void* gsrc) {
    unsigned s = (unsigned)__cvta_generic_to_shared(smem_dst);
    asm volatile("cp.async.cg.shared.global [%0], [%1], 16;\n" :: "r"(s), "l"(gsrc));
}
#define CP_COMMIT() asm volatile("cp.async.commit_group;\n" ::: "memory")
#define CP_WAIT(N)  asm volatile("cp.async.wait_group %0;\n" :: "n"(N) : "memory")

__device__ __forceinline__ unsigned pack_h2(float lo, float hi) {
    __half2 h = __floats2half2_rn(lo, hi);
    return *(unsigned*)&h;
}

// ---------------- fp16 tensor-core GEMM ----------------
// C = A @ B + bias, B supplied TRANSPOSED ([N][K] fp16).
// BM=128 fixed, BN templated (128 or 64), BK=32, 256 threads,
// 8 warps as 4(m) x 2(n); warp tile 32 x BN/2. 3-stage cp.async pipeline.
#define GA_ST 40   // halves per A row (32 + 8 pad)
#define GB_ST 40

template<int BN, typename OutT>
__global__ __launch_bounds__(256) void mma_gemm(
        const __half* __restrict__ A0, const __half* __restrict__ Bt0,
        const float* __restrict__ bi0, OutT* __restrict__ C0,
        const __half* __restrict__ A1, const __half* __restrict__ Bt1,
        const float* __restrict__ bi1, OutT* __restrict__ C1,
        int M, int N, int K) {
    const __half* A    = blockIdx.z ? A1 : A0;
    const __half* Bt   = blockIdx.z ? Bt1 : Bt0;
    const float*  bias = blockIdx.z ? bi1 : bi0;
    OutT*         C    = blockIdx.z ? C1 : C0;

    constexpr int NJ = BN / 16;                    // mma j-steps per warp
    constexpr int STAGE_HALVES = 128 * GA_ST + BN * GB_ST;

    extern __shared__ __half gsm[];

    const int tid  = threadIdx.x;
    const int lane = tid & 31;
    const int wid  = tid >> 5;
    const int wm   = wid & 3;
    const int wn   = wid >> 2;
    const int g    = lane >> 2;
    const int qq   = lane & 3;

    const int row0 = blockIdx.y * 128;
    const int col0 = blockIdx.x * BN;
    const int nst  = K / 32;

    auto issue = [&](int ks) {
        __half* As = gsm + (ks % 3) * STAGE_HALVES;
        __half* Bs = As + 128 * GA_ST;
        int k0 = ks * 32;
        #pragma unroll
        for (int i = tid; i < 512; i += 256) {
            int row = i >> 2, c = i & 3;
            cp16(As + row * GA_ST + 8 * c, A + (long)(row0 + row) * K + k0 + 8 * c);
        }
        #pragma unroll
        for (int i = tid; i < BN * 4; i += 256) {
            int row = i >> 2, c = i & 3;
            cp16(Bs + row * GB_ST + 8 * c, Bt + (long)(col0 + row) * K + k0 + 8 * c);
        }
    };

    float acc[2][NJ][4];
    #pragma unroll
    for (int mi = 0; mi < 2; mi++)
        #pragma unroll
        for (int j = 0; j < NJ; j++)
            #pragma unroll
            for (int e = 0; e < 4; e++) acc[mi][j][e] = 0.0f;

    issue(0); CP_COMMIT();
    issue(1); CP_COMMIT();

    for (int ks = 0; ks < nst; ks++) {
        CP_WAIT(1);
        __syncthreads();
        if (ks + 2 < nst) issue(ks + 2);
        CP_COMMIT();

        const __half* As = gsm + (ks % 3) * STAGE_HALVES;
        const __half* Bs = As + 128 * GA_ST;

        #pragma unroll
        for (int kk = 0; kk < 2; kk++) {
            unsigned a[2][4];
            #pragma unroll
            for (int mi = 0; mi < 2; mi++) {
                int m = 32 * wm + 16 * mi;
                a[mi][0] = *(const unsigned*)&As[(m + g    ) * GA_ST + 16 * kk + 2 * qq];
                a[mi][1] = *(const unsigned*)&As[(m + g + 8) * GA_ST + 16 * kk + 2 * qq];
                a[mi][2] = *(const unsigned*)&As[(m + g    ) * GA_ST + 16 * kk + 2 * qq + 8];
                a[mi][3] = *(const unsigned*)&As[(m + g + 8) * GA_ST + 16 * kk + 2 * qq + 8];
            }
            #pragma unroll
            for (int j = 0; j < NJ; j++) {
                const __half* bb = &Bs[((BN / 2) * wn + 8 * j + g) * GB_ST + 16 * kk + 2 * qq];
                unsigned b[2];
                b[0] = *(const unsigned*)(bb);
                b[1] = *(const unsigned*)(bb + 8);
                mma_f16(acc[0][j], a[0], b);
                mma_f16(acc[1][j], a[1], b);
            }
        }
        __syncthreads();
    }

    #pragma unroll
    for (int mi = 0; mi < 2; mi++) {
        int row = row0 + 32 * wm + 16 * mi + g;
        #pragma unroll
        for (int j = 0; j < NJ; j++) {
            int col = col0 + (BN / 2) * wn + 8 * j + 2 * qq;
            float b0 = bias[col], b1 = bias[col + 1];
            float v00 = acc[mi][j][0] + b0, v01 = acc[mi][j][1] + b1;
            float v10 = acc[mi][j][2] + b0, v11 = acc[mi][j][3] + b1;
            if (sizeof(OutT) == 2) {
                *(__half2*)((__half*)C + (long)row * N + col)       = __floats2half2_rn(v00, v01);
                *(__half2*)((__half*)C + (long)(row + 8) * N + col) = __floats2half2_rn(v10, v11);
            } else {
                *(float2*)((float*)C + (long)row * N + col)       = make_float2(v00, v01);
                *(float2*)((float*)C + (long)(row + 8) * N + col) = make_float2(v10, v11);
            }
        }
    }
}

// ---------------- input conversion ----------------
__global__ void convert_x(const float4* __restrict__ x, __half2* __restrict__ xh) {
    int i = blockIdx.x * 256 + threadIdx.x;
    float4 v = x[i];
    xh[2 * i]     = __floats2half2_rn(v.x, v.y);
    xh[2 * i + 1] = __floats2half2_rn(v.z, v.w);
}

// fused weight transpose+convert: 1536 blocks of (32,8)
__global__ void prep_weights(const float* __restrict__ wdk, const float* __restrict__ wdv,
                             const float* __restrict__ wuk, const float* __restrict__ wuv,
                             const float* __restrict__ wo,
                             __half* __restrict__ wdkT, __half* __restrict__ wdvT,
                             __half* __restrict__ wukT, __half* __restrict__ wuvT,
                             __half* __restrict__ woT) {
    __shared__ float tile[32][33];
    int id = blockIdx.x;
    const float* src; __half* dst; int R, Cn, bx, by;
    if (id < 256) {                 // wdk/wdv: [1024][128] -> [128][1024]
        int w = id >> 7, rm = id & 127;
        src = w ? wdv : wdk; dst = w ? wdvT : wdkT;
        R = 1024; Cn = 128; bx = rm & 3; by = rm >> 2;
    } else if (id < 512) {          // wuk/wuv: [128][1024] -> [1024][128]
        int w = (id - 256) >> 7, rm = (id - 256) & 127;
        src = w ? wuv : wuk; dst = w ? wuvT : wukT;
        R = 128; Cn = 1024; bx = rm & 31; by = rm >> 5;
    } else {                        // w_o: [1024][1024]
        int rm = id - 512;
        src = wo; dst = woT;
        R = 1024; Cn = 1024; bx = rm & 31; by = rm >> 5;
    }
    int c0 = bx * 32, r0 = by * 32;
    int tx = threadIdx.x, ty = threadIdx.y;
    #pragma unroll
    for (int i = 0; i < 4; i++)
        tile[ty + 8 * i][tx] = src[(long)(r0 + ty + 8 * i) * Cn + c0 + tx];
    __syncthreads();
    #pragma unroll
    for (int i = 0; i < 4; i++)
        dst[(long)(c0 + ty + 8 * i) * R + r0 + tx] = __float2half(tile[tx][ty + 8 * i]);
}

// ---------------- RoPE + head split + V transpose ----------------
// Per thread: fixed d, t steps by 4 -> sin/cos rotation recurrence.
#define VS_T_ST 68
__global__ void prepare_qkv(const __half* __restrict__ xh,
                            const __half* __restrict__ kf,
                            const __half* __restrict__ vf,
                            __half* __restrict__ qh,
                            __half* __restrict__ kh,
                            __half* __restrict__ vt) {
    __shared__ __half vs[64][VS_T_ST];
    const int tid = threadIdx.x;
    const int t0  = blockIdx.x * 64;
    const int bh  = blockIdx.y;
    const int b   = bh >> 4;
    const int h   = bh & 15;

    const int d   = tid & 63;        // fixed across iterations
    const int tl0 = tid >> 6;        // 0..3
    const int i2  = d & 31;

    // inv_freq = 10000^(-i2/32) = exp2(-i2 * log2(10000)/32)
    float inv_freq = exp2f(-(float)i2 * 0.41524101186092f);
    float sv, cv, S4, C4;
    sincosf((float)(t0 + tl0) * inv_freq, &sv, &cv);
    sincosf(4.0f * inv_freq, &S4, &C4);

    #pragma unroll
    for (int it = 0; it < 16; it++) {
        int tl = tl0 + 4 * it;
        int t = t0 + tl;
        long src = ((long)(b * Tc + t)) * Dc + h * DHc + d;

        float xv = __half2float(xh[src]);
        float xr = (d < 32) ? -__half2float(xh[src + 32]) : __half2float(xh[src - 32]);
        long dst = ((long)bh * Tc + t) * DHc + d;
        qh[dst] = __float2half(xv * cv + xr * sv);

        float kv = __half2float(kf[src]);
        float kr = (d < 32) ? -__half2float(kf[src + 32]) : __half2float(kf[src - 32]);
        kh[dst] = __float2half(kv * cv + kr * sv);

        vs[d][tl] = vf[src];

        float c2 = cv * C4 - sv * S4;
        float s2 = sv * C4 + cv * S4;
        cv = c2; sv = s2;
    }
    __syncthreads();
    #pragma unroll
    for (int it = 0; it < 16; it++) {
        int idx = it * 256 + tid;
        int dd = idx >> 6, tl = idx & 63;
        vt[((long)bh * DHc + dd) * Tc + t0 + tl] = vs[dd][tl];
    }
}

// ---------------- flash attention, fp16 mma (unchanged from R5) ----------------
#define KS_ST 72
#define VT_ST 72
#define ATT_BUF_HALVES (64 * KS_ST + 64 * VT_ST)
#define ATT_SMEM_BYTES (3 * ATT_BUF_HALVES * 2)

__global__ __launch_bounds__(256, 2) void attn_kernel(
        const __half* __restrict__ qh,
        const __half* __restrict__ kh,
        const __half* __restrict__ vt,
        __half* __restrict__ out) {
    extern __shared__ __half sma[];

    const int tid  = threadIdx.x;
    const int lane = tid & 31;
    const int w    = tid >> 5;
    const int g    = lane >> 2;
    const int qq   = lane & 3;

    const int bh = blockIdx.y;
    const int b  = bh >> 4;
    const int h  = bh & 15;
    const int t0 = blockIdx.x * 128;

    const __half* qp = qh + ((long)bh * Tc + t0) * DHc;
    const __half* kp = kh + (long)bh * Tc * DHc;
    const __half* vp = vt + (long)bh * DHc * Tc;

    unsigned qa[4][4];
    #pragma unroll
    for (int kk = 0; kk < 4; kk++) {
        qa[kk][0] = *(const unsigned*)&qp[(16 * w + g    ) * 64 + 16 * kk + 2 * qq];
        qa[kk][1] = *(const unsigned*)&qp[(16 * w + g + 8) * 64 + 16 * kk + 2 * qq];
        qa[kk][2] = *(const unsigned*)&qp[(16 * w + g    ) * 64 + 16 * kk + 2 * qq + 8];
        qa[kk][3] = *(const unsigned*)&qp[(16 * w + g + 8) * 64 + 16 * kk + 2 * qq + 8];
    }

    auto issue = [&](int tile) {
        __half* Kd = sma + (tile % 3) * ATT_BUF_HALVES;
        __half* Vd = Kd + 64 * KS_ST;
        int kt = tile * 64;
        #pragma unroll
        for (int i = tid; i < 512; i += 256) {
            int r = i >> 3, c = i & 7;
            cp16(Kd + r * KS_ST + 8 * c, kp + (long)(kt + r) * 64 + 8 * c);
            cp16(Vd + r * VT_ST + 8 * c, vp + (long)r * Tc + kt + 8 * c);
        }
    };

    float o[8][4];
    #pragma unroll
    for (int j = 0; j < 8; j++)
        #pragma unroll
        for (int e = 0; e < 4; e++) o[j][e] = 0.0f;
    float m_i[2] = {-1e30f, -1e30f};
    float l_i[2] = {0.0f, 0.0f};

    issue(0); CP_COMMIT();
    issue(1); CP_COMMIT();

    for (int it = 0; it < 32; it++) {
        CP_WAIT(1);
        __syncthreads();
        if (it + 2 < 32) issue(it + 2);
        CP_COMMIT();

        const __half* Ku = sma + (it % 3) * ATT_BUF_HALVES;
        const __half* Vu = Ku + 64 * KS_ST;

        float s[8][4];
        #pragma unroll
        for (int j = 0; j < 8; j++)
            #pragma unroll
            for (int e = 0; e < 4; e++) s[j][e] = 0.0f;
        #pragma unroll
        for (int kk = 0; kk < 4; kk++) {
            #pragma unroll
            for (int j = 0; j < 8; j++) {
                const __half* bb = &Ku[(8 * j + g) * KS_ST + 16 * kk + 2 * qq];
                unsigned bfr[2];
                bfr[0] = *(const unsigned*)(bb);
                bfr[1] = *(const unsigned*)(bb + 8);
                mma_f16(s[j], qa[kk], bfr);
            }
        }

        #pragma unroll
        for (int hh = 0; hh < 2; hh++) {
            float mt = -1e30f;
            #pragma unroll
            for (int j = 0; j < 8; j++) {
                s[j][2 * hh]     *= 0.125f;
                s[j][2 * hh + 1] *= 0.125f;
                mt = fmaxf(mt, fmaxf(s[j][2 * hh], s[j][2 * hh + 1]));
            }
            mt = fmaxf(mt, __shfl_xor_sync(0xffffffffu, mt, 1));
            mt = fmaxf(mt, __shfl_xor_sync(0xffffffffu, mt, 2));

            float mnew = fmaxf(m_i[hh], mt);
            float corr = __expf(m_i[hh] - mnew);
            float lsum = 0.0f;
            #pragma unroll
            for (int j = 0; j < 8; j++) {
                float p0 = __expf(s[j][2 * hh]     - mnew);
                float p1 = __expf(s[j][2 * hh + 1] - mnew);
                s[j][2 * hh]     = p0;
                s[j][2 * hh + 1] = p1;
                lsum += p0 + p1;
            }
            lsum += __shfl_xor_sync(0xffffffffu, lsum, 1);
            lsum += __shfl_xor_sync(0xffffffffu, lsum, 2);

            l_i[hh] = l_i[hh] * corr + lsum;
            m_i[hh] = mnew;
            #pragma unroll
            for (int j = 0; j < 8; j++) {
                o[j][2 * hh]     *= corr;
                o[j][2 * hh + 1] *= corr;
            }
        }

        #pragma unroll
        for (int kk = 0; kk < 4; kk++) {
            unsigned pa[4];
            pa[0] = pack_h2(s[2 * kk][0],     s[2 * kk][1]);
            pa[1] = pack_h2(s[2 * kk][2],     s[2 * kk][3]);
            pa[2] = pack_h2(s[2 * kk + 1][0], s[2 * kk + 1][1]);
            pa[3] = pack_h2(s[2 * kk + 1][2], s[2 * kk + 1][3]);
            #pragma unroll
            for (int j = 0; j < 8; j++) {
                const __half* bb = &Vu[(8 * j + g) * VT_ST + 16 * kk + 2 * qq];
                unsigned bfr[2];
                bfr[0] = *(const unsigned*)(bb);
                bfr[1] = *(const unsigned*)(bb + 8);
                mma_f16(o[j], pa, bfr);
            }
        }
    }

    float inv0 = 1.0f / l_i[0];
    float inv1 = 1.0f / l_i[1];
    int t_r0 = t0 + 16 * w + g;
    long base0 = ((long)b * Tc + t_r0) * Dc + h * DHc;
    long base1 = ((long)b * Tc + t_r0 + 8) * Dc + h * DHc;
    #pragma unroll
    for (int j = 0; j < 8; j++) {
        int col = 8 * j + 2 * qq;
        *(__half2*)&out[base0 + col] = __floats2half2_rn(o[j][0] * inv0, o[j][1] * inv0);
        *(__half2*)&out[base1 + col] = __floats2half2_rn(o[j][2] * inv1, o[j][3] * inv1);
    }
}

// ---------------- launch ----------------
#define G_SMEM_128 (3 * (128 * GA_ST + 128 * GB_ST) * 2)   // 61440
#define G_SMEM_64  (3 * (128 * GA_ST + 64 * GB_ST) * 2)    // 46080

extern "C" void kernel_launch(void* const* d_in, const int* in_sizes, int n_in,
                              void* d_out, int out_size) {
    const float* x    = (const float*)d_in[0];
    const float* w_dk = (const float*)d_in[1];
    const float* b_dk = (const float*)d_in[2];
    const float* w_dv = (const float*)d_in[3];
    const float* b_dv = (const float*)d_in[4];
    const float* w_uk = (const float*)d_in[5];
    const float* b_uk = (const float*)d_in[6];
    const float* w_uv = (const float*)d_in[7];
    const float* b_uv = (const float*)d_in[8];
    const float* w_o  = (const float*)d_in[9];
    const float* b_o  = (const float*)d_in[10];
    float* out = (float*)d_out;

    __half *xh, *wdkT, *wdvT, *wukT, *wuvT, *woT, *ck, *cv, *kf, *vf, *qh, *kh, *vt, *ao;
    cudaGetSymbolAddress((void**)&xh,   g_xh);
    cudaGetSymbolAddress((void**)&wdkT, g_wdkT);
    cudaGetSymbolAddress((void**)&wdvT, g_wdvT);
    cudaGetSymbolAddress((void**)&wukT, g_wukT);
    cudaGetSymbolAddress((void**)&wuvT, g_wuvT);
    cudaGetSymbolAddress((void**)&woT,  g_woT);
    cudaGetSymbolAddress((void**)&ck,   g_ck);
    cudaGetSymbolAddress((void**)&cv,   g_cv);
    cudaGetSymbolAddress((void**)&kf,   g_kf);
    cudaGetSymbolAddress((void**)&vf,   g_vf);
    cudaGetSymbolAddress((void**)&qh,   g_qh);
    cudaGetSymbolAddress((void**)&kh,   g_kh);
    cudaGetSymbolAddress((void**)&vt,   g_vt);
    cudaGetSymbolAddress((void**)&ao,   g_ao);

    static int attrs_set = 0;
    if (!attrs_set) {
        cudaFuncSetAttribute((const void*)mma_gemm<64,  __half>, cudaFuncAttributeMaxDynamicSharedMemorySize, G_SMEM_64);
        cudaFuncSetAttribute((const void*)mma_gemm<128, __half>, cudaFuncAttributeMaxDynamicSharedMemorySize, G_SMEM_128);
        cudaFuncSetAttribute((const void*)mma_gemm<128, float>,  cudaFuncAttributeMaxDynamicSharedMemorySize, G_SMEM_128);
        cudaFuncSetAttribute((const void*)attn_kernel, cudaFuncAttributeMaxDynamicSharedMemorySize, ATT_SMEM_BYTES);
        attrs_set = 1;
    }

    dim3 blk(256);

    // convert x; transpose+convert all weights (one launch)
    convert_x<<<4096, 256>>>((const float4*)x, (__half2*)xh);
    prep_weights<<<1536, dim3(32, 8)>>>(w_dk, w_dv, w_uk, w_uv, w_o,
                                        wdkT, wdvT, wukT, wuvT, woT);

    // down-projections: (BT x 1024) @ (1024 x 128) -> fp16 ck/cv  [BN=64: 128 CTAs]
    mma_gemm<64, __half><<<dim3(Cc / 64, BT / 128, 2), blk, G_SMEM_64>>>(
        xh, wdkT, b_dk, ck, xh, wdvT, b_dv, cv, BT, Cc, Dc);

    // up-projections: (BT x 128) @ (128 x 1024) -> fp16 kf/vf
    mma_gemm<128, __half><<<dim3(Dc / 128, BT / 128, 2), blk, G_SMEM_128>>>(
        ck, wukT, b_uk, kf, cv, wuvT, b_uv, vf, BT, Dc, Cc);

    // RoPE + head split + V transpose
    prepare_qkv<<<dim3(Tc / 64, Bc * Hc), blk>>>(xh, kf, vf, qh, kh, vt);

    // attention (HMMA, unchanged from R5)
    attn_kernel<<<dim3(Tc / 128, Bc * Hc), blk, ATT_SMEM_BYTES>>>(qh, kh, vt, ao);

    // output projection: (BT x 1024) @ (1024 x 1024) -> fp32 out
    mma_gemm<128, float><<<dim3(Dc / 128, BT / 128, 1), blk, G_SMEM_128>>>(
        ao, woT, b_o, out, ao, woT, b_o, out, BT, Dc, Dc);
}

// round 8
// speedup vs baseline: 8.0122x; 1.1245x over previous
#include <cuda_runtime.h>
#include <cuda_fp16.h>
#include <math.h>
#include <stdint.h>

// Problem constants
#define Bc   2
#define Tc   2048
#define Dc   1024
#define Hc   16
#define DHc  64
#define Cc   128
#define BT   4096   // B*T

// ---------------- scratch (no allocations allowed) ----------------
__device__ __half g_xh  [BT * Dc];      // x in fp16
__device__ __half g_wdkT[Cc * Dc];      // w_dk^T fp16 [C][D]
__device__ __half g_wdvT[Cc * Dc];
__device__ __half g_wukT[Dc * Cc];      // w_uk^T fp16 [D][C]
__device__ __half g_wuvT[Dc * Cc];
__device__ __half g_woT [Dc * Dc];      // w_o^T fp16
__device__ __half g_ck  [BT * Cc];      // fp16
__device__ __half g_cv  [BT * Cc];
__device__ __half g_kf  [BT * Dc];      // fp16 pre-rope
__device__ __half g_vf  [BT * Dc];
__device__ __half g_qh  [BT * Dc];      // [B,H,T,DH] fp16 (pre-scaled by 0.125*log2e)
__device__ __half g_kh  [BT * Dc];      // [B,H,T,DH] fp16
__device__ __half g_vt  [BT * Dc];      // [B,H,DH,T] fp16 (V transposed)
__device__ __half g_ao  [BT * Dc];      // attention out [B,T,D] fp16

// ---------------- helpers ----------------
__device__ __forceinline__ void mma_f16(float c[4], const unsigned a[4], const unsigned b[2]) {
    asm volatile(
        "mma.sync.aligned.m16n8k16.row.col.f32.f16.f16.f32 "
        "{%0,%1,%2,%3}, {%4,%5,%6,%7}, {%8,%9}, {%0,%1,%2,%3};"
        : "+f"(c[0]), "+f"(c[1]), "+f"(c[2]), "+f"(c[3])
        : "r"(a[0]), "r"(a[1]), "r"(a[2]), "r"(a[3]), "r"(b[0]), "r"(b[1]));
}

__device__ __forceinline__ void ldsm_x4(unsigned& d0, unsigned& d1, unsigned& d2, unsigned& d3,
                                        const __half* p) {
    unsigned a = (unsigned)__cvta_generic_to_shared(p);
    asm volatile("ldmatrix.sync.aligned.m8n8.x4.shared.b16 {%0,%1,%2,%3}, [%4];"
                 : "=r"(d0), "=r"(d1), "=r"(d2), "=r"(d3) : "r"(a));
}

__device__ __forceinline__ void cp16(void* smem_dst, const void* gsrc) {
    unsigned s = (unsigned)__cvta_generic_to_shared(smem_dst);
    asm volatile("cp.async.cg.shared.global [%0], [%1], 16;\n" :: "r"(s), "l"(gsrc));
}
#define CP_COMMIT() asm volatile("cp.async.commit_group;\n" ::: "memory")
#define CP_WAIT(N)  asm volatile("cp.async.wait_group %0;\n" :: "n"(N) : "memory")

__device__ __forceinline__ unsigned pack_h2(float lo, float hi) {
    __half2 h = __floats2half2_rn(lo, hi);
    return *(unsigned*)&h;
}

__device__ __forceinline__ float fexp2(float x) {
    float y;
    asm("ex2.approx.ftz.f32 %0, %1;" : "=f"(y) : "f"(x));
    return y;
}

// ---------------- fp16 tensor-core GEMM ----------------
// C = A @ B + bias, B supplied TRANSPOSED ([N][K] fp16).
// BM=128 fixed, BN templated (128 or 64), BK=32, 256 threads,
// 8 warps as 4(m) x 2(n); warp tile 32 x BN/2. 3-stage cp.async, ldmatrix frags.
#define GA_ST 40   // halves per A row (32 + 8 pad)
#define GB_ST 40

template<int BN, typename OutT>
__global__ __launch_bounds__(256) void mma_gemm(
        const __half* __restrict__ A0, const __half* __restrict__ Bt0,
        const float* __restrict__ bi0, OutT* __restrict__ C0,
        const __half* __restrict__ A1, const __half* __restrict__ Bt1,
        const float* __restrict__ bi1, OutT* __restrict__ C1,
        int M, int N, int K) {
    const __half* A    = blockIdx.z ? A1 : A0;
    const __half* Bt   = blockIdx.z ? Bt1 : Bt0;
    const float*  bias = blockIdx.z ? bi1 : bi0;
    OutT*         C    = blockIdx.z ? C1 : C0;

    constexpr int NJ = BN / 16;                    // mma j-steps per warp
    constexpr int STAGE_HALVES = 128 * GA_ST + BN * GB_ST;

    extern __shared__ __half gsm[];

    const int tid  = threadIdx.x;
    const int lane = tid & 31;
    const int wid  = tid >> 5;
    const int wm   = wid & 3;
    const int wn   = wid >> 2;
    const int g    = lane >> 2;
    const int qq   = lane & 3;

    // ldmatrix lane addressing
    const int a_lrow = 8 * ((lane >> 3) & 1) + (lane & 7);   // A: mats (m-lo,m-hi)x(k-lo,k-hi)
    const int a_koff = 8 * (lane >> 4);
    const int b_lrow = 8 * ((lane >> 4) & 1) + (lane & 7);   // B: mats (k-lo,k-hi)x(n-lo,n-hi)
    const int b_koff = 8 * ((lane >> 3) & 1);

    const int row0 = blockIdx.y * 128;
    const int col0 = blockIdx.x * BN;
    const int nst  = K / 32;

    auto issue = [&](int ks) {
        __half* As = gsm + (ks % 3) * STAGE_HALVES;
        __half* Bs = As + 128 * GA_ST;
        int k0 = ks * 32;
        #pragma unroll
        for (int i = tid; i < 512; i += 256) {
            int row = i >> 2, c = i & 3;
            cp16(As + row * GA_ST + 8 * c, A + (long)(row0 + row) * K + k0 + 8 * c);
        }
        #pragma unroll
        for (int i = tid; i < BN * 4; i += 256) {
            int row = i >> 2, c = i & 3;
            cp16(Bs + row * GB_ST + 8 * c, Bt + (long)(col0 + row) * K + k0 + 8 * c);
        }
    };

    float acc[2][NJ][4];
    #pragma unroll
    for (int mi = 0; mi < 2; mi++)
        #pragma unroll
        for (int j = 0; j < NJ; j++)
            #pragma unroll
            for (int e = 0; e < 4; e++) acc[mi][j][e] = 0.0f;

    issue(0); CP_COMMIT();
    issue(1); CP_COMMIT();

    for (int ks = 0; ks < nst; ks++) {
        CP_WAIT(1);
        __syncthreads();
        if (ks + 2 < nst) issue(ks + 2);
        CP_COMMIT();

        const __half* As = gsm + (ks % 3) * STAGE_HALVES;
        const __half* Bs = As + 128 * GA_ST;

        #pragma unroll
        for (int kk = 0; kk < 2; kk++) {
            unsigned a[2][4];
            #pragma unroll
            for (int mi = 0; mi < 2; mi++)
                ldsm_x4(a[mi][0], a[mi][1], a[mi][2], a[mi][3],
                        &As[(32 * wm + 16 * mi + a_lrow) * GA_ST + 16 * kk + a_koff]);
            unsigned bq[NJ][2];
            #pragma unroll
            for (int p = 0; p < NJ / 2; p++)
                ldsm_x4(bq[2 * p][0], bq[2 * p][1], bq[2 * p + 1][0], bq[2 * p + 1][1],
                        &Bs[((BN / 2) * wn + 16 * p + b_lrow) * GB_ST + 16 * kk + b_koff]);
            #pragma unroll
            for (int j = 0; j < NJ; j++) {
                mma_f16(acc[0][j], a[0], bq[j]);
                mma_f16(acc[1][j], a[1], bq[j]);
            }
        }
        __syncthreads();
    }

    #pragma unroll
    for (int mi = 0; mi < 2; mi++) {
        int row = row0 + 32 * wm + 16 * mi + g;
        #pragma unroll
        for (int j = 0; j < NJ; j++) {
            int col = col0 + (BN / 2) * wn + 8 * j + 2 * qq;
            float b0 = bias[col], b1 = bias[col + 1];
            float v00 = acc[mi][j][0] + b0, v01 = acc[mi][j][1] + b1;
            float v10 = acc[mi][j][2] + b0, v11 = acc[mi][j][3] + b1;
            if (sizeof(OutT) == 2) {
                *(__half2*)((__half*)C + (long)row * N + col)       = __floats2half2_rn(v00, v01);
                *(__half2*)((__half*)C + (long)(row + 8) * N + col) = __floats2half2_rn(v10, v11);
            } else {
                *(float2*)((float*)C + (long)row * N + col)       = make_float2(v00, v01);
                *(float2*)((float*)C + (long)(row + 8) * N + col) = make_float2(v10, v11);
            }
        }
    }
}

// ---------------- input conversion ----------------
__global__ void convert_x(const float4* __restrict__ x, __half2* __restrict__ xh) {
    int i = blockIdx.x * 256 + threadIdx.x;
    float4 v = x[i];
    xh[2 * i]     = __floats2half2_rn(v.x, v.y);
    xh[2 * i + 1] = __floats2half2_rn(v.z, v.w);
}

// fused weight transpose+convert: 1536 blocks of (32,8)
__global__ void prep_weights(const float* __restrict__ wdk, const float* __restrict__ wdv,
                             const float* __restrict__ wuk, const float* __restrict__ wuv,
                             const float* __restrict__ wo,
                             __half* __restrict__ wdkT, __half* __restrict__ wdvT,
                             __half* __restrict__ wukT, __half* __restrict__ wuvT,
                             __half* __restrict__ woT) {
    __shared__ float tile[32][33];
    int id = blockIdx.x;
    const float* src; __half* dst; int R, Cn, bx, by;
    if (id < 256) {                 // wdk/wdv: [1024][128] -> [128][1024]
        int w = id >> 7, rm = id & 127;
        src = w ? wdv : wdk; dst = w ? wdvT : wdkT;
        R = 1024; Cn = 128; bx = rm & 3; by = rm >> 2;
    } else if (id < 512) {          // wuk/wuv: [128][1024] -> [1024][128]
        int w = (id - 256) >> 7, rm = (id - 256) & 127;
        src = w ? wuv : wuk; dst = w ? wuvT : wukT;
        R = 128; Cn = 1024; bx = rm & 31; by = rm >> 5;
    } else {                        // w_o: [1024][1024]
        int rm = id - 512;
        src = wo; dst = woT;
        R = 1024; Cn = 1024; bx = rm & 31; by = rm >> 5;
    }
    int c0 = bx * 32, r0 = by * 32;
    int tx = threadIdx.x, ty = threadIdx.y;
    #pragma unroll
    for (int i = 0; i < 4; i++)
        tile[ty + 8 * i][tx] = src[(long)(r0 + ty + 8 * i) * Cn + c0 + tx];
    __syncthreads();
    #pragma unroll
    for (int i = 0; i < 4; i++)
        dst[(long)(c0 + ty + 8 * i) * R + r0 + tx] = __float2half(tile[tx][ty + 8 * i]);
}

// ---------------- RoPE + head split + V transpose ----------------
// Q is pre-scaled by softmax_scale * log2(e) so attention runs in log2 domain.
#define QSCL 0.18033688011112042f   // 0.125 * log2(e)
#define VS_T_ST 68
__global__ void prepare_qkv(const __half* __restrict__ xh,
                            const __half* __restrict__ kf,
                            const __half* __restrict__ vf,
                            __half* __restrict__ qh,
                            __half* __restrict__ kh,
                            __half* __restrict__ vt) {
    __shared__ __half vs[64][VS_T_ST];
    const int tid = threadIdx.x;
    const int t0  = blockIdx.x * 64;
    const int bh  = blockIdx.y;
    const int b   = bh >> 4;
    const int h   = bh & 15;

    const int d   = tid & 63;
    const int tl0 = tid >> 6;
    const int i2  = d & 31;

    float inv_freq = exp2f(-(float)i2 * 0.41524101186092f);
    float sv, cv, S4, C4;
    sincosf((float)(t0 + tl0) * inv_freq, &sv, &cv);
    sincosf(4.0f * inv_freq, &S4, &C4);

    #pragma unroll
    for (int it = 0; it < 16; it++) {
        int tl = tl0 + 4 * it;
        int t = t0 + tl;
        long src = ((long)(b * Tc + t)) * Dc + h * DHc + d;

        float xv = __half2float(xh[src]);
        float xr = (d < 32) ? -__half2float(xh[src + 32]) : __half2float(xh[src - 32]);
        long dst = ((long)bh * Tc + t) * DHc + d;
        qh[dst] = __float2half((xv * cv + xr * sv) * QSCL);

        float kv = __half2float(kf[src]);
        float kr = (d < 32) ? -__half2float(kf[src + 32]) : __half2float(kf[src - 32]);
        kh[dst] = __float2half(kv * cv + kr * sv);

        vs[d][tl] = vf[src];

        float c2 = cv * C4 - sv * S4;
        float s2 = sv * C4 + cv * S4;
        cv = c2; sv = s2;
    }
    __syncthreads();
    #pragma unroll
    for (int it = 0; it < 16; it++) {
        int idx = it * 256 + tid;
        int dd = idx >> 6, tl = idx & 63;
        vt[((long)bh * DHc + dd) * Tc + t0 + tl] = vs[dd][tl];
    }
}

// ---------------- flash attention, fp16 mma + ldmatrix, log2 softmax ----------------
#define KS_ST 72
#define VT_ST 72
#define ATT_BUF_HALVES (64 * KS_ST + 64 * VT_ST)
#define ATT_SMEM_BYTES (3 * ATT_BUF_HALVES * 2)

__global__ __launch_bounds__(256, 2) void attn_kernel(
        const __half* __restrict__ qh,
        const __half* __restrict__ kh,
        const __half* __restrict__ vt,
        __half* __restrict__ out) {
    extern __shared__ __half sma[];

    const int tid  = threadIdx.x;
    const int lane = tid & 31;
    const int w    = tid >> 5;
    const int g    = lane >> 2;
    const int qq   = lane & 3;

    const int b_lrow = 8 * ((lane >> 4) & 1) + (lane & 7);
    const int b_koff = 8 * ((lane >> 3) & 1);

    const int bh = blockIdx.y;
    const int b  = bh >> 4;
    const int h  = bh & 15;
    const int t0 = blockIdx.x * 128;

    const __half* qp = qh + ((long)bh * Tc + t0) * DHc;
    const __half* kp = kh + (long)bh * Tc * DHc;
    const __half* vp = vt + (long)bh * DHc * Tc;

    unsigned qa[4][4];
    #pragma unroll
    for (int kk = 0; kk < 4; kk++) {
        qa[kk][0] = *(const unsigned*)&qp[(16 * w + g    ) * 64 + 16 * kk + 2 * qq];
        qa[kk][1] = *(const unsigned*)&qp[(16 * w + g + 8) * 64 + 16 * kk + 2 * qq];
        qa[kk][2] = *(const unsigned*)&qp[(16 * w + g    ) * 64 + 16 * kk + 2 * qq + 8];
        qa[kk][3] = *(const unsigned*)&qp[(16 * w + g + 8) * 64 + 16 * kk + 2 * qq + 8];
    }

    auto issue = [&](int tile) {
        __half* Kd = sma + (tile % 3) * ATT_BUF_HALVES;
        __half* Vd = Kd + 64 * KS_ST;
        int kt = tile * 64;
        #pragma unroll
        for (int i = tid; i < 512; i += 256) {
            int r = i >> 3, c = i & 7;
            cp16(Kd + r * KS_ST + 8 * c, kp + (long)(kt + r) * 64 + 8 * c);
            cp16(Vd + r * VT_ST + 8 * c, vp + (long)r * Tc + kt + 8 * c);
        }
    };

    float o[8][4];
    #pragma unroll
    for (int j = 0; j < 8; j++)
        #pragma unroll
        for (int e = 0; e < 4; e++) o[j][e] = 0.0f;
    float m_i[2] = {-1e30f, -1e30f};
    float l_i[2] = {0.0f, 0.0f};

    issue(0); CP_COMMIT();
    issue(1); CP_COMMIT();

    for (int it = 0; it < 32; it++) {
        CP_WAIT(1);
        __syncthreads();
        if (it + 2 < 32) issue(it + 2);
        CP_COMMIT();

        const __half* Ku = sma + (it % 3) * ATT_BUF_HALVES;
        const __half* Vu = Ku + 64 * KS_ST;

        // S = Q @ K^T (already in log2 domain via Q pre-scale)
        float s[8][4];
        #pragma unroll
        for (int j = 0; j < 8; j++)
            #pragma unroll
            for (int e = 0; e < 4; e++) s[j][e] = 0.0f;
        #pragma unroll
        for (int kk = 0; kk < 4; kk++) {
            unsigned bq[8][2];
            #pragma unroll
            for (int p = 0; p < 4; p++)
                ldsm_x4(bq[2 * p][0], bq[2 * p][1], bq[2 * p + 1][0], bq[2 * p + 1][1],
                        &Ku[(16 * p + b_lrow) * KS_ST + 16 * kk + b_koff]);
            #pragma unroll
            for (int j = 0; j < 8; j++)
                mma_f16(s[j], qa[kk], bq[j]);
        }

        // online softmax, base-2
        #pragma unroll
        for (int hh = 0; hh < 2; hh++) {
            float mt = -1e30f;
            #pragma unroll
            for (int j = 0; j < 8; j++)
                mt = fmaxf(mt, fmaxf(s[j][2 * hh], s[j][2 * hh + 1]));
            mt = fmaxf(mt, __shfl_xor_sync(0xffffffffu, mt, 1));
            mt = fmaxf(mt, __shfl_xor_sync(0xffffffffu, mt, 2));

            float mnew = fmaxf(m_i[hh], mt);
            float corr = fexp2(m_i[hh] - mnew);
            float lsum = 0.0f;
            #pragma unroll
            for (int j = 0; j < 8; j++) {
                float p0 = fexp2(s[j][2 * hh]     - mnew);
                float p1 = fexp2(s[j][2 * hh + 1] - mnew);
                s[j][2 * hh]     = p0;
                s[j][2 * hh + 1] = p1;
                lsum += p0 + p1;
            }
            lsum += __shfl_xor_sync(0xffffffffu, lsum, 1);
            lsum += __shfl_xor_sync(0xffffffffu, lsum, 2);

            l_i[hh] = l_i[hh] * corr + lsum;
            m_i[hh] = mnew;
            #pragma unroll
            for (int j = 0; j < 8; j++) {
                o[j][2 * hh]     *= corr;
                o[j][2 * hh + 1] *= corr;
            }
        }

        // O += P @ V
        #pragma unroll
        for (int kk = 0; kk < 4; kk++) {
            unsigned pa[4];
            pa[0] = pack_h2(s[2 * kk][0],     s[2 * kk][1]);
            pa[1] = pack_h2(s[2 * kk][2],     s[2 * kk][3]);
            pa[2] = pack_h2(s[2 * kk + 1][0], s[2 * kk + 1][1]);
            pa[3] = pack_h2(s[2 * kk + 1][2], s[2 * kk + 1][3]);
            unsigned bq[8][2];
            #pragma unroll
            for (int p = 0; p < 4; p++)
                ldsm_x4(bq[2 * p][0], bq[2 * p][1], bq[2 * p + 1][0], bq[2 * p + 1][1],
                        &Vu[(16 * p + b_lrow) * VT_ST + 16 * kk + b_koff]);
            #pragma unroll
            for (int j = 0; j < 8; j++)
                mma_f16(o[j], pa, bq[j]);
        }
    }

    float inv0 = 1.0f / l_i[0];
    float inv1 = 1.0f / l_i[1];
    int t_r0 = t0 + 16 * w + g;
    long base0 = ((long)b * Tc + t_r0) * Dc + h * DHc;
    long base1 = ((long)b * Tc + t_r0 + 8) * Dc + h * DHc;
    #pragma unroll
    for (int j = 0; j < 8; j++) {
        int col = 8 * j + 2 * qq;
        *(__half2*)&out[base0 + col] = __floats2half2_rn(o[j][0] * inv0, o[j][1] * inv0);
        *(__half2*)&out[base1 + col] = __floats2half2_rn(o[j][2] * inv1, o[j][3] * inv1);
    }
}

// ---------------- launch ----------------
#define G_SMEM_128 (3 * (128 * GA_ST + 128 * GB_ST) * 2)   // 61440
#define G_SMEM_64  (3 * (128 * GA_ST + 64 * GB_ST) * 2)    // 46080

extern "C" void kernel_launch(void* const* d_in, const int* in_sizes, int n_in,
                              void* d_out, int out_size) {
    const float* x    = (const float*)d_in[0];
    const float* w_dk = (const float*)d_in[1];
    const float* b_dk = (const float*)d_in[2];
    const float* w_dv = (const float*)d_in[3];
    const float* b_dv = (const float*)d_in[4];
    const float* w_uk = (const float*)d_in[5];
    const float* b_uk = (const float*)d_in[6];
    const float* w_uv = (const float*)d_in[7];
    const float* b_uv = (const float*)d_in[8];
    const float* w_o  = (const float*)d_in[9];
    const float* b_o  = (const float*)d_in[10];
    float* out = (float*)d_out;

    __half *xh, *wdkT, *wdvT, *wukT, *wuvT, *woT, *ck, *cv, *kf, *vf, *qh, *kh, *vt, *ao;
    cudaGetSymbolAddress((void**)&xh,   g_xh);
    cudaGetSymbolAddress((void**)&wdkT, g_wdkT);
    cudaGetSymbolAddress((void**)&wdvT, g_wdvT);
    cudaGetSymbolAddress((void**)&wukT, g_wukT);
    cudaGetSymbolAddress((void**)&wuvT, g_wuvT);
    cudaGetSymbolAddress((void**)&woT,  g_woT);
    cudaGetSymbolAddress((void**)&ck,   g_ck);
    cudaGetSymbolAddress((void**)&cv,   g_cv);
    cudaGetSymbolAddress((void**)&kf,   g_kf);
    cudaGetSymbolAddress((void**)&vf,   g_vf);
    cudaGetSymbolAddress((void**)&qh,   g_qh);
    cudaGetSymbolAddress((void**)&kh,   g_kh);
    cudaGetSymbolAddress((void**)&vt,   g_vt);
    cudaGetSymbolAddress((void**)&ao,   g_ao);

    static int attrs_set = 0;
    if (!attrs_set) {
        cudaFuncSetAttribute((const void*)mma_gemm<64,  __half>, cudaFuncAttributeMaxDynamicSharedMemorySize, G_SMEM_64);
        cudaFuncSetAttribute((const void*)mma_gemm<128, __half>, cudaFuncAttributeMaxDynamicSharedMemorySize, G_SMEM_128);
        cudaFuncSetAttribute((const void*)mma_gemm<128, float>,  cudaFuncAttributeMaxDynamicSharedMemorySize, G_SMEM_128);
        cudaFuncSetAttribute((const void*)attn_kernel, cudaFuncAttributeMaxDynamicSharedMemorySize, ATT_SMEM_BYTES);
        attrs_set = 1;
    }

    dim3 blk(256);

    convert_x<<<4096, 256>>>((const float4*)x, (__half2*)xh);
    prep_weights<<<1536, dim3(32, 8)>>>(w_dk, w_dv, w_uk, w_uv, w_o,
                                        wdkT, wdvT, wukT, wuvT, woT);

    // down-projections: (BT x 1024) @ (1024 x 128) -> fp16 ck/cv  [BN=64]
    mma_gemm<64, __half><<<dim3(Cc / 64, BT / 128, 2), blk, G_SMEM_64>>>(
        xh, wdkT, b_dk, ck, xh, wdvT, b_dv, cv, BT, Cc, Dc);

    // up-projections: (BT x 128) @ (128 x 1024) -> fp16 kf/vf
    mma_gemm<128, __half><<<dim3(Dc / 128, BT / 128, 2), blk, G_SMEM_128>>>(
        ck, wukT, b_uk, kf, cv, wuvT, b_uv, vf, BT, Dc, Cc);

    // RoPE + head split + V transpose (Q pre-scaled)
    prepare_qkv<<<dim3(Tc / 64, Bc * Hc), blk>>>(xh, kf, vf, qh, kh, vt);

    // attention
    attn_kernel<<<dim3(Tc / 128, Bc * Hc), blk, ATT_SMEM_BYTES>>>(qh, kh, vt, ao);

    // output projection: (BT x 1024) @ (1024 x 1024) -> fp32 out
    mma_gemm<128, float><<<dim3(Dc / 128, BT / 128, 1), blk, G_SMEM_128>>>(
        ao, woT, b_o, out, ao, woT, b_o, out, BT, Dc, Dc);
}

// round 9
// speedup vs baseline: 8.1716x; 1.0199x over previous
#include <cuda_runtime.h>
#include <cuda_fp16.h>
#include <math.h>
#include <stdint.h>

// Problem constants
#define Bc   2
#define Tc   2048
#define Dc   1024
#define Hc   16
#define DHc  64
#define Cc   128
#define BT   4096   // B*T

// ---------------- scratch (no allocations allowed) ----------------
__device__ __half g_xh  [BT * Dc];
__device__ __half g_wdkT[Cc * Dc];
__device__ __half g_wdvT[Cc * Dc];
__device__ __half g_wukT[Dc * Cc];
__device__ __half g_wuvT[Dc * Cc];
__device__ __half g_woT [Dc * Dc];
__device__ __half g_ck  [BT * Cc];
__device__ __half g_cv  [BT * Cc];
__device__ __half g_kf  [BT * Dc];
__device__ __half g_vf  [BT * Dc];
__device__ __half g_qh  [BT * Dc];      // [B,H,T,DH] fp16 (pre-scaled by 0.125*log2e)
__device__ __half g_kh  [BT * Dc];
__device__ __half g_vt  [BT * Dc];      // [B,H,DH,T]
__device__ __half g_ao  [BT * Dc];

// ---------------- helpers ----------------
__device__ __forceinline__ void mma_f16(float c[4], const unsigned a[4], const unsigned b[2]) {
    asm volatile(
        "mma.sync.aligned.m16n8k16.row.col.f32.f16.f16.f32 "
        "{%0,%1,%2,%3}, {%4,%5,%6,%7}, {%8,%9}, {%0,%1,%2,%3};"
        : "+f"(c[0]), "+f"(c[1]), "+f"(c[2]), "+f"(c[3])
        : "r"(a[0]), "r"(a[1]), "r"(a[2]), "r"(a[3]), "r"(b[0]), "r"(b[1]));
}

__device__ __forceinline__ void ldsm_x4(unsigned& d0, unsigned& d1, unsigned& d2, unsigned& d3,
                                        const __half* p) {
    unsigned a = (unsigned)__cvta_generic_to_shared(p);
    asm volatile("ldmatrix.sync.aligned.m8n8.x4.shared.b16 {%0,%1,%2,%3}, [%4];"
                 : "=r"(d0), "=r"(d1), "=r"(d2), "=r"(d3) : "r"(a));
}

__device__ __forceinline__ void cp16(void* smem_dst, const void* gsrc) {
    unsigned s = (unsigned)__cvta_generic_to_shared(smem_dst);
    asm volatile("cp.async.cg.shared.global [%0], [%1], 16;\n" :: "r"(s), "l"(gsrc));
}
#define CP_COMMIT() asm volatile("cp.async.commit_group;\n" ::: "memory")
#define CP_WAIT(N)  asm volatile("cp.async.wait_group %0;\n" :: "n"(N) : "memory")

__device__ __forceinline__ unsigned pack_h2(float lo, float hi) {
    __half2 h = __floats2half2_rn(lo, hi);
    return *(unsigned*)&h;
}

__device__ __forceinline__ float fexp2(float x) {
    float y;
    asm("ex2.approx.ftz.f32 %0, %1;" : "=f"(y) : "f"(x));
    return y;
}

// ---------------- fp16 tensor-core GEMM ----------------
// C = A @ B + bias, B supplied TRANSPOSED ([N][K] fp16).
// BM=128, BN=64, BK=32, 256 threads, 8 warps 4(m)x2(n), warp tile 32x32.
// 3-stage cp.async, ldmatrix frags. __launch_bounds__(256,3) for 24 warps/SM.
#define GA_ST 40   // halves per row (32 + 8 pad)
#define GB_ST 40
#define GBN   64
#define G_NJ  (GBN / 16)
#define G_STAGE_HALVES (128 * GA_ST + GBN * GB_ST)
#define G_SMEM_BYTES   (3 * G_STAGE_HALVES * 2)     // 46080

template<typename OutT>
__global__ __launch_bounds__(256, 3) void mma_gemm(
        const __half* __restrict__ A0, const __half* __restrict__ Bt0,
        const float* __restrict__ bi0, OutT* __restrict__ C0,
        const __half* __restrict__ A1, const __half* __restrict__ Bt1,
        const float* __restrict__ bi1, OutT* __restrict__ C1,
        int M, int N, int K) {
    const __half* A    = blockIdx.z ? A1 : A0;
    const __half* Bt   = blockIdx.z ? Bt1 : Bt0;
    const float*  bias = blockIdx.z ? bi1 : bi0;
    OutT*         C    = blockIdx.z ? C1 : C0;

    extern __shared__ __half gsm[];

    const int tid  = threadIdx.x;
    const int lane = tid & 31;
    const int wid  = tid >> 5;
    const int wm   = wid & 3;
    const int wn   = wid >> 2;
    const int g    = lane >> 2;
    const int qq   = lane & 3;

    const int a_lrow = 8 * ((lane >> 3) & 1) + (lane & 7);
    const int a_koff = 8 * (lane >> 4);
    const int b_lrow = 8 * ((lane >> 4) & 1) + (lane & 7);
    const int b_koff = 8 * ((lane >> 3) & 1);

    const int row0 = blockIdx.y * 128;
    const int col0 = blockIdx.x * GBN;
    const int nst  = K / 32;

    auto issue = [&](int ks) {
        __half* As = gsm + (ks % 3) * G_STAGE_HALVES;
        __half* Bs = As + 128 * GA_ST;
        int k0 = ks * 32;
        #pragma unroll
        for (int i = tid; i < 512; i += 256) {
            int row = i >> 2, c = i & 3;
            cp16(As + row * GA_ST + 8 * c, A + (long)(row0 + row) * K + k0 + 8 * c);
        }
        {
            int row = tid >> 2, c = tid & 3;
            cp16(Bs + row * GB_ST + 8 * c, Bt + (long)(col0 + row) * K + k0 + 8 * c);
        }
    };

    float acc[2][G_NJ][4];
    #pragma unroll
    for (int mi = 0; mi < 2; mi++)
        #pragma unroll
        for (int j = 0; j < G_NJ; j++)
            #pragma unroll
            for (int e = 0; e < 4; e++) acc[mi][j][e] = 0.0f;

    issue(0); CP_COMMIT();
    issue(1); CP_COMMIT();

    for (int ks = 0; ks < nst; ks++) {
        CP_WAIT(1);
        __syncthreads();
        if (ks + 2 < nst) issue(ks + 2);
        CP_COMMIT();

        const __half* As = gsm + (ks % 3) * G_STAGE_HALVES;
        const __half* Bs = As + 128 * GA_ST;

        #pragma unroll
        for (int kk = 0; kk < 2; kk++) {
            unsigned a[2][4];
            #pragma unroll
            for (int mi = 0; mi < 2; mi++)
                ldsm_x4(a[mi][0], a[mi][1], a[mi][2], a[mi][3],
                        &As[(32 * wm + 16 * mi + a_lrow) * GA_ST + 16 * kk + a_koff]);
            unsigned bq[G_NJ][2];
            #pragma unroll
            for (int p = 0; p < G_NJ / 2; p++)
                ldsm_x4(bq[2 * p][0], bq[2 * p][1], bq[2 * p + 1][0], bq[2 * p + 1][1],
                        &Bs[((GBN / 2) * wn + 16 * p + b_lrow) * GB_ST + 16 * kk + b_koff]);
            #pragma unroll
            for (int j = 0; j < G_NJ; j++) {
                mma_f16(acc[0][j], a[0], bq[j]);
                mma_f16(acc[1][j], a[1], bq[j]);
            }
        }
        __syncthreads();
    }

    #pragma unroll
    for (int mi = 0; mi < 2; mi++) {
        int row = row0 + 32 * wm + 16 * mi + g;
        #pragma unroll
        for (int j = 0; j < G_NJ; j++) {
            int col = col0 + (GBN / 2) * wn + 8 * j + 2 * qq;
            float b0 = bias[col], b1 = bias[col + 1];
            float v00 = acc[mi][j][0] + b0, v01 = acc[mi][j][1] + b1;
            float v10 = acc[mi][j][2] + b0, v11 = acc[mi][j][3] + b1;
            if (sizeof(OutT) == 2) {
                *(__half2*)((__half*)C + (long)row * N + col)       = __floats2half2_rn(v00, v01);
                *(__half2*)((__half*)C + (long)(row + 8) * N + col) = __floats2half2_rn(v10, v11);
            } else {
                *(float2*)((float*)C + (long)row * N + col)       = make_float2(v00, v01);
                *(float2*)((float*)C + (long)(row + 8) * N + col) = make_float2(v10, v11);
            }
        }
    }
}

// ---------------- input conversion ----------------
__global__ void convert_x(const float4* __restrict__ x, __half2* __restrict__ xh) {
    int i = blockIdx.x * 256 + threadIdx.x;
    float4 v = x[i];
    xh[2 * i]     = __floats2half2_rn(v.x, v.y);
    xh[2 * i + 1] = __floats2half2_rn(v.z, v.w);
}

__global__ void prep_weights(const float* __restrict__ wdk, const float* __restrict__ wdv,
                             const float* __restrict__ wuk, const float* __restrict__ wuv,
                             const float* __restrict__ wo,
                             __half* __restrict__ wdkT, __half* __restrict__ wdvT,
                             __half* __restrict__ wukT, __half* __restrict__ wuvT,
                             __half* __restrict__ woT) {
    __shared__ float tile[32][33];
    int id = blockIdx.x;
    const float* src; __half* dst; int R, Cn, bx, by;
    if (id < 256) {
        int w = id >> 7, rm = id & 127;
        src = w ? wdv : wdk; dst = w ? wdvT : wdkT;
        R = 1024; Cn = 128; bx = rm & 3; by = rm >> 2;
    } else if (id < 512) {
        int w = (id - 256) >> 7, rm = (id - 256) & 127;
        src = w ? wuv : wuk; dst = w ? wuvT : wukT;
        R = 128; Cn = 1024; bx = rm & 31; by = rm >> 5;
    } else {
        int rm = id - 512;
        src = wo; dst = woT;
        R = 1024; Cn = 1024; bx = rm & 31; by = rm >> 5;
    }
    int c0 = bx * 32, r0 = by * 32;
    int tx = threadIdx.x, ty = threadIdx.y;
    #pragma unroll
    for (int i = 0; i < 4; i++)
        tile[ty + 8 * i][tx] = src[(long)(r0 + ty + 8 * i) * Cn + c0 + tx];
    __syncthreads();
    #pragma unroll
    for (int i = 0; i < 4; i++)
        dst[(long)(c0 + ty + 8 * i) * R + r0 + tx] = __float2half(tile[tx][ty + 8 * i]);
}

// ---------------- RoPE + head split + V transpose ----------------
#define QSCL 0.18033688011112042f   // 0.125 * log2(e)
#define VS_T_ST 68
__global__ void prepare_qkv(const __half* __restrict__ xh,
                            const __half* __restrict__ kf,
                            const __half* __restrict__ vf,
                            __half* __restrict__ qh,
                            __half* __restrict__ kh,
                            __half* __restrict__ vt) {
    __shared__ __half vs[64][VS_T_ST];
    const int tid = threadIdx.x;
    const int t0  = blockIdx.x * 64;
    const int bh  = blockIdx.y;
    const int b   = bh >> 4;
    const int h   = bh & 15;

    const int d   = tid & 63;
    const int tl0 = tid >> 6;
    const int i2  = d & 31;

    float inv_freq = exp2f(-(float)i2 * 0.41524101186092f);
    float sv, cv, S4, C4;
    sincosf((float)(t0 + tl0) * inv_freq, &sv, &cv);
    sincosf(4.0f * inv_freq, &S4, &C4);

    #pragma unroll
    for (int it = 0; it < 16; it++) {
        int tl = tl0 + 4 * it;
        int t = t0 + tl;
        long src = ((long)(b * Tc + t)) * Dc + h * DHc + d;

        float xv = __half2float(xh[src]);
        float xr = (d < 32) ? -__half2float(xh[src + 32]) : __half2float(xh[src - 32]);
        long dst = ((long)bh * Tc + t) * DHc + d;
        qh[dst] = __float2half((xv * cv + xr * sv) * QSCL);

        float kv = __half2float(kf[src]);
        float kr = (d < 32) ? -__half2float(kf[src + 32]) : __half2float(kf[src - 32]);
        kh[dst] = __float2half(kv * cv + kr * sv);

        vs[d][tl] = vf[src];

        float c2 = cv * C4 - sv * S4;
        float s2 = sv * C4 + cv * S4;
        cv = c2; sv = s2;
    }
    __syncthreads();
    #pragma unroll
    for (int it = 0; it < 16; it++) {
        int idx = it * 256 + tid;
        int dd = idx >> 6, tl = idx & 63;
        vt[((long)bh * DHc + dd) * Tc + t0 + tl] = vs[dd][tl];
    }
}

// ---------------- flash attention: 4 warps x m32, ldmatrix, log2 softmax ----------------
// 128 threads/CTA, q-tile 128 rows (32/warp), 64-key tiles, 3-stage cp.async.
// Each K/V fragment feeds 2 MMAs (halved LDSM redundancy vs m16 warps).
#define KS_ST 72
#define VT_ST 72
#define ATT_BUF_HALVES (64 * KS_ST + 64 * VT_ST)
#define ATT_SMEM_BYTES (3 * ATT_BUF_HALVES * 2)

__global__ __launch_bounds__(128, 2) void attn_kernel(
        const __half* __restrict__ qh,
        const __half* __restrict__ kh,
        const __half* __restrict__ vt,
        __half* __restrict__ out) {
    extern __shared__ __half sma[];

    const int tid  = threadIdx.x;
    const int lane = tid & 31;
    const int w    = tid >> 5;        // 0..3, q rows [32w, 32w+32)
    const int g    = lane >> 2;
    const int qq   = lane & 3;

    const int b_lrow = 8 * ((lane >> 4) & 1) + (lane & 7);
    const int b_koff = 8 * ((lane >> 3) & 1);

    const int bh = blockIdx.y;
    const int b  = bh >> 4;
    const int h  = bh & 15;
    const int t0 = blockIdx.x * 128;

    const __half* qp = qh + ((long)bh * Tc + t0) * DHc;
    const __half* kp = kh + (long)bh * Tc * DHc;
    const __half* vp = vt + (long)bh * DHc * Tc;

    // Q fragments: 4 k16-steps x 2 m16-tiles x 4 regs
    unsigned qa[4][2][4];
    #pragma unroll
    for (int kk = 0; kk < 4; kk++)
        #pragma unroll
        for (int mt = 0; mt < 2; mt++) {
            int r0 = 32 * w + 16 * mt;
            qa[kk][mt][0] = *(const unsigned*)&qp[(r0 + g    ) * 64 + 16 * kk + 2 * qq];
            qa[kk][mt][1] = *(const unsigned*)&qp[(r0 + g + 8) * 64 + 16 * kk + 2 * qq];
            qa[kk][mt][2] = *(const unsigned*)&qp[(r0 + g    ) * 64 + 16 * kk + 2 * qq + 8];
            qa[kk][mt][3] = *(const unsigned*)&qp[(r0 + g + 8) * 64 + 16 * kk + 2 * qq + 8];
        }

    auto issue = [&](int tile) {
        __half* Kd = sma + (tile % 3) * ATT_BUF_HALVES;
        __half* Vd = Kd + 64 * KS_ST;
        int kt = tile * 64;
        #pragma unroll
        for (int i = tid; i < 512; i += 128) {
            int r = i >> 3, c = i & 7;
            cp16(Kd + r * KS_ST + 8 * c, kp + (long)(kt + r) * 64 + 8 * c);
            cp16(Vd + r * VT_ST + 8 * c, vp + (long)r * Tc + kt + 8 * c);
        }
    };

    float o[2][8][4];
    #pragma unroll
    for (int mt = 0; mt < 2; mt++)
        #pragma unroll
        for (int j = 0; j < 8; j++)
            #pragma unroll
            for (int e = 0; e < 4; e++) o[mt][j][e] = 0.0f;
    float m_i[2][2] = {{-1e30f, -1e30f}, {-1e30f, -1e30f}};
    float l_i[2][2] = {{0.0f, 0.0f}, {0.0f, 0.0f}};

    issue(0); CP_COMMIT();
    issue(1); CP_COMMIT();

    for (int it = 0; it < 32; it++) {
        CP_WAIT(1);
        __syncthreads();
        if (it + 2 < 32) issue(it + 2);
        CP_COMMIT();

        const __half* Ku = sma + (it % 3) * ATT_BUF_HALVES;
        const __half* Vu = Ku + 64 * KS_ST;

        // S = Q @ K^T (log2 domain via Q pre-scale)
        float s[2][8][4];
        #pragma unroll
        for (int mt = 0; mt < 2; mt++)
            #pragma unroll
            for (int j = 0; j < 8; j++)
                #pragma unroll
                for (int e = 0; e < 4; e++) s[mt][j][e] = 0.0f;
        #pragma unroll
        for (int kk = 0; kk < 4; kk++) {
            unsigned bq[8][2];
            #pragma unroll
            for (int p = 0; p < 4; p++)
                ldsm_x4(bq[2 * p][0], bq[2 * p][1], bq[2 * p + 1][0], bq[2 * p + 1][1],
                        &Ku[(16 * p + b_lrow) * KS_ST + 16 * kk + b_koff]);
            #pragma unroll
            for (int j = 0; j < 8; j++) {
                mma_f16(s[0][j], qa[kk][0], bq[j]);
                mma_f16(s[1][j], qa[kk][1], bq[j]);
            }
        }

        // online softmax, base-2, per (m16-tile, row-half)
        #pragma unroll
        for (int mt = 0; mt < 2; mt++)
            #pragma unroll
            for (int hh = 0; hh < 2; hh++) {
                float mt_ = -1e30f;
                #pragma unroll
                for (int j = 0; j < 8; j++)
                    mt_ = fmaxf(mt_, fmaxf(s[mt][j][2 * hh], s[mt][j][2 * hh + 1]));
                mt_ = fmaxf(mt_, __shfl_xor_sync(0xffffffffu, mt_, 1));
                mt_ = fmaxf(mt_, __shfl_xor_sync(0xffffffffu, mt_, 2));

                float mnew = fmaxf(m_i[mt][hh], mt_);
                float corr = fexp2(m_i[mt][hh] - mnew);
                float lsum = 0.0f;
                #pragma unroll
                for (int j = 0; j < 8; j++) {
                    float p0 = fexp2(s[mt][j][2 * hh]     - mnew);
                    float p1 = fexp2(s[mt][j][2 * hh + 1] - mnew);
                    s[mt][j][2 * hh]     = p0;
                    s[mt][j][2 * hh + 1] = p1;
                    lsum += p0 + p1;
                }
                lsum += __shfl_xor_sync(0xffffffffu, lsum, 1);
                lsum += __shfl_xor_sync(0xffffffffu, lsum, 2);

                l_i[mt][hh] = l_i[mt][hh] * corr + lsum;
                m_i[mt][hh] = mnew;
                #pragma unroll
                for (int j = 0; j < 8; j++) {
                    o[mt][j][2 * hh]     *= corr;
                    o[mt][j][2 * hh + 1] *= corr;
                }
            }

        // O += P @ V
        #pragma unroll
        for (int kk = 0; kk < 4; kk++) {
            unsigned pa[2][4];
            #pragma unroll
            for (int mt = 0; mt < 2; mt++) {
                pa[mt][0] = pack_h2(s[mt][2 * kk][0],     s[mt][2 * kk][1]);
                pa[mt][1] = pack_h2(s[mt][2 * kk][2],     s[mt][2 * kk][3]);
                pa[mt][2] = pack_h2(s[mt][2 * kk + 1][0], s[mt][2 * kk + 1][1]);
                pa[mt][3] = pack_h2(s[mt][2 * kk + 1][2], s[mt][2 * kk + 1][3]);
            }
            unsigned bq[8][2];
            #pragma unroll
            for (int p = 0; p < 4; p++)
                ldsm_x4(bq[2 * p][0], bq[2 * p][1], bq[2 * p + 1][0], bq[2 * p + 1][1],
                        &Vu[(16 * p + b_lrow) * VT_ST + 16 * kk + b_koff]);
            #pragma unroll
            for (int j = 0; j < 8; j++) {
                mma_f16(o[0][j], pa[0], bq[j]);
                mma_f16(o[1][j], pa[1], bq[j]);
            }
        }
    }

    // epilogue
    #pragma unroll
    for (int mt = 0; mt < 2; mt++) {
        float inv0 = 1.0f / l_i[mt][0];
        float inv1 = 1.0f / l_i[mt][1];
        int t_r0 = t0 + 32 * w + 16 * mt + g;
        long base0 = ((long)b * Tc + t_r0) * Dc + h * DHc;
        long base1 = ((long)b * Tc + t_r0 + 8) * Dc + h * DHc;
        #pragma unroll
        for (int j = 0; j < 8; j++) {
            int col = 8 * j + 2 * qq;
            *(__half2*)&out[base0 + col] = __floats2half2_rn(o[mt][j][0] * inv0, o[mt][j][1] * inv0);
            *(__half2*)&out[base1 + col] = __floats2half2_rn(o[mt][j][2] * inv1, o[mt][j][3] * inv1);
        }
    }
}

// ---------------- launch ----------------
extern "C" void kernel_launch(void* const* d_in, const int* in_sizes, int n_in,
                              void* d_out, int out_size) {
    const float* x    = (const float*)d_in[0];
    const float* w_dk = (const float*)d_in[1];
    const float* b_dk = (const float*)d_in[2];
    const float* w_dv = (const float*)d_in[3];
    const float* b_dv = (const float*)d_in[4];
    const float* w_uk = (const float*)d_in[5];
    const float* b_uk = (const float*)d_in[6];
    const float* w_uv = (const float*)d_in[7];
    const float* b_uv = (const float*)d_in[8];
    const float* w_o  = (const float*)d_in[9];
    const float* b_o  = (const float*)d_in[10];
    float* out = (float*)d_out;

    __half *xh, *wdkT, *wdvT, *wukT, *wuvT, *woT, *ck, *cv, *kf, *vf, *qh, *kh, *vt, *ao;
    cudaGetSymbolAddress((void**)&xh,   g_xh);
    cudaGetSymbolAddress((void**)&wdkT, g_wdkT);
    cudaGetSymbolAddress((void**)&wdvT, g_wdvT);
    cudaGetSymbolAddress((void**)&wukT, g_wukT);
    cudaGetSymbolAddress((void**)&wuvT, g_wuvT);
    cudaGetSymbolAddress((void**)&woT,  g_woT);
    cudaGetSymbolAddress((void**)&ck,   g_ck);
    cudaGetSymbolAddress((void**)&cv,   g_cv);
    cudaGetSymbolAddress((void**)&kf,   g_kf);
    cudaGetSymbolAddress((void**)&vf,   g_vf);
    cudaGetSymbolAddress((void**)&qh,   g_qh);
    cudaGetSymbolAddress((void**)&kh,   g_kh);
    cudaGetSymbolAddress((void**)&vt,   g_vt);
    cudaGetSymbolAddress((void**)&ao,   g_ao);

    static int attrs_set = 0;
    if (!attrs_set) {
        cudaFuncSetAttribute((const void*)mma_gemm<__half>, cudaFuncAttributeMaxDynamicSharedMemorySize, G_SMEM_BYTES);
        cudaFuncSetAttribute((const void*)mma_gemm<float>,  cudaFuncAttributeMaxDynamicSharedMemorySize, G_SMEM_BYTES);
        cudaFuncSetAttribute((const void*)attn_kernel, cudaFuncAttributeMaxDynamicSharedMemorySize, ATT_SMEM_BYTES);
        attrs_set = 1;
    }

    convert_x<<<4096, 256>>>((const float4*)x, (__half2*)xh);
    prep_weights<<<1536, dim3(32, 8)>>>(w_dk, w_dv, w_uk, w_uv, w_o,
                                        wdkT, wdvT, wukT, wuvT, woT);

    // down-projections: (BT x 1024) @ (1024 x 128) -> fp16 ck/cv
    mma_gemm<__half><<<dim3(Cc / GBN, BT / 128, 2), 256, G_SMEM_BYTES>>>(
        xh, wdkT, b_dk, ck, xh, wdvT, b_dv, cv, BT, Cc, Dc);

    // up-projections: (BT x 128) @ (128 x 1024) -> fp16 kf/vf
    mma_gemm<__half><<<dim3(Dc / GBN, BT / 128, 2), 256, G_SMEM_BYTES>>>(
        ck, wukT, b_uk, kf, cv, wuvT, b_uv, vf, BT, Dc, Cc);

    // RoPE + head split + V transpose (Q pre-scaled)
    prepare_qkv<<<dim3(Tc / 64, Bc * Hc), 256>>>(xh, kf, vf, qh, kh, vt);

    // attention: 128 threads, 4 warps x m32
    attn_kernel<<<dim3(Tc / 128, Bc * Hc), 128, ATT_SMEM_BYTES>>>(qh, kh, vt, ao);

    // output projection: (BT x 1024) @ (1024 x 1024) -> fp32 out
    mma_gemm<float><<<dim3(Dc / GBN, BT / 128, 1), 256, G_SMEM_BYTES>>>(
        ao, woT, b_o, out, ao, woT, b_o, out, BT, Dc, Dc);
}

// round 10
// speedup vs baseline: 8.3624x; 1.0233x over previous
#include <cuda_runtime.h>
#include <cuda_fp16.h>
#include <math.h>
#include <stdint.h>

// Problem constants
#define Bc   2
#define Tc   2048
#define Dc   1024
#define Hc   16
#define DHc  64
#define Cc   128
#define BT   4096   // B*T

// ---------------- scratch (no allocations allowed) ----------------
__device__ __half g_xh  [BT * Dc];
__device__ __half g_wdkT[Cc * Dc];
__device__ __half g_wdvT[Cc * Dc];
__device__ __half g_wukT[Dc * Cc];
__device__ __half g_wuvT[Dc * Cc];
__device__ __half g_woT [Dc * Dc];
__device__ __half g_ck  [BT * Cc];
__device__ __half g_cv  [BT * Cc];
__device__ __half g_kf  [BT * Dc];
__device__ __half g_vf  [BT * Dc];
__device__ __half g_qh  [BT * Dc];      // [B,H,T,DH] fp16 (pre-scaled by 0.125*log2e)
__device__ __half g_kh  [BT * Dc];
__device__ __half g_vt  [BT * Dc];      // [B,H,DH,T]
__device__ __half g_ao  [BT * Dc];

// ---------------- helpers ----------------
__device__ __forceinline__ void mma_f16(float c[4], const unsigned a[4], const unsigned b[2]) {
    asm volatile(
        "mma.sync.aligned.m16n8k16.row.col.f32.f16.f16.f32 "
        "{%0,%1,%2,%3}, {%4,%5,%6,%7}, {%8,%9}, {%0,%1,%2,%3};"
        : "+f"(c[0]), "+f"(c[1]), "+f"(c[2]), "+f"(c[3])
        : "r"(a[0]), "r"(a[1]), "r"(a[2]), "r"(a[3]), "r"(b[0]), "r"(b[1]));
}

__device__ __forceinline__ void ldsm_x4(unsigned& d0, unsigned& d1, unsigned& d2, unsigned& d3,
                                        const __half* p) {
    unsigned a = (unsigned)__cvta_generic_to_shared(p);
    asm volatile("ldmatrix.sync.aligned.m8n8.x4.shared.b16 {%0,%1,%2,%3}, [%4];"
                 : "=r"(d0), "=r"(d1), "=r"(d2), "=r"(d3) : "r"(a));
}

__device__ __forceinline__ void cp16(void* smem_dst, const void* gsrc) {
    unsigned s = (unsigned)__cvta_generic_to_shared(smem_dst);
    asm volatile("cp.async.cg.shared.global [%0], [%1], 16;\n" :: "r"(s), "l"(gsrc));
}
#define CP_COMMIT() asm volatile("cp.async.commit_group;\n" ::: "memory")
#define CP_WAIT(N)  asm volatile("cp.async.wait_group %0;\n" :: "n"(N) : "memory")

__device__ __forceinline__ unsigned pack_h2(float lo, float hi) {
    __half2 h = __floats2half2_rn(lo, hi);
    return *(unsigned*)&h;
}

__device__ __forceinline__ float fexp2(float x) {
    float y;
    asm("ex2.approx.ftz.f32 %0, %1;" : "=f"(y) : "f"(x));
    return y;
}

// ---------------- fp16 tensor-core GEMM (pipelined, long K) ----------------
// C = A @ B + bias, B supplied TRANSPOSED ([N][K] fp16).
// BM=64*MI, BN=64, BK=32, 256 threads, 8 warps 4(m)x2(n), warp tile 16*MI x 32.
#define GA_ST 40   // halves per row (32 + 8 pad)
#define GB_ST 40
#define GBN   64
#define G_NJ  (GBN / 16)

template<int MI, typename OutT>
__global__ __launch_bounds__(256, 3) void mma_gemm(
        const __half* __restrict__ A0, const __half* __restrict__ Bt0,
        const float* __restrict__ bi0, OutT* __restrict__ C0,
        const __half* __restrict__ A1, const __half* __restrict__ Bt1,
        const float* __restrict__ bi1, OutT* __restrict__ C1,
        int M, int N, int K) {
    const __half* A    = blockIdx.z ? A1 : A0;
    const __half* Bt   = blockIdx.z ? Bt1 : Bt0;
    const float*  bias = blockIdx.z ? bi1 : bi0;
    OutT*         C    = blockIdx.z ? C1 : C0;

    constexpr int BM = 64 * MI;
    constexpr int STAGE_HALVES = (BM + GBN) * GA_ST;

    extern __shared__ __half gsm[];

    const int tid  = threadIdx.x;
    const int lane = tid & 31;
    const int wid  = tid >> 5;
    const int wm   = wid & 3;
    const int wn   = wid >> 2;
    const int g    = lane >> 2;
    const int qq   = lane & 3;

    const int a_lrow = 8 * ((lane >> 3) & 1) + (lane & 7);
    const int a_koff = 8 * (lane >> 4);
    const int b_lrow = 8 * ((lane >> 4) & 1) + (lane & 7);
    const int b_koff = 8 * ((lane >> 3) & 1);

    const int row0 = blockIdx.y * BM;
    const int col0 = blockIdx.x * GBN;
    const int nst  = K / 32;

    auto issue = [&](int ks) {
        __half* As = gsm + (ks % 3) * STAGE_HALVES;
        __half* Bs = As + BM * GA_ST;
        int k0 = ks * 32;
        #pragma unroll
        for (int i = tid; i < BM * 4; i += 256) {
            int row = i >> 2, c = i & 3;
            cp16(As + row * GA_ST + 8 * c, A + (long)(row0 + row) * K + k0 + 8 * c);
        }
        {
            int row = tid >> 2, c = tid & 3;
            cp16(Bs + row * GB_ST + 8 * c, Bt + (long)(col0 + row) * K + k0 + 8 * c);
        }
    };

    float acc[MI][G_NJ][4];
    #pragma unroll
    for (int mi = 0; mi < MI; mi++)
        #pragma unroll
        for (int j = 0; j < G_NJ; j++)
            #pragma unroll
            for (int e = 0; e < 4; e++) acc[mi][j][e] = 0.0f;

    issue(0); CP_COMMIT();
    issue(1); CP_COMMIT();

    for (int ks = 0; ks < nst; ks++) {
        CP_WAIT(1);
        __syncthreads();
        if (ks + 2 < nst) issue(ks + 2);
        CP_COMMIT();

        const __half* As = gsm + (ks % 3) * STAGE_HALVES;
        const __half* Bs = As + BM * GA_ST;

        #pragma unroll
        for (int kk = 0; kk < 2; kk++) {
            unsigned a[MI][4];
            #pragma unroll
            for (int mi = 0; mi < MI; mi++)
                ldsm_x4(a[mi][0], a[mi][1], a[mi][2], a[mi][3],
                        &As[(16 * (MI * wm + mi) + a_lrow) * GA_ST + 16 * kk + a_koff]);
            unsigned bq[G_NJ][2];
            #pragma unroll
            for (int p = 0; p < G_NJ / 2; p++)
                ldsm_x4(bq[2 * p][0], bq[2 * p][1], bq[2 * p + 1][0], bq[2 * p + 1][1],
                        &Bs[(32 * wn + 16 * p + b_lrow) * GB_ST + 16 * kk + b_koff]);
            #pragma unroll
            for (int j = 0; j < G_NJ; j++)
                #pragma unroll
                for (int mi = 0; mi < MI; mi++)
                    mma_f16(acc[mi][j], a[mi], bq[j]);
        }
        __syncthreads();
    }

    #pragma unroll
    for (int mi = 0; mi < MI; mi++) {
        int row = row0 + 16 * (MI * wm + mi) + g;
        #pragma unroll
        for (int j = 0; j < G_NJ; j++) {
            int col = col0 + 32 * wn + 8 * j + 2 * qq;
            float b0 = bias[col], b1 = bias[col + 1];
            float v00 = acc[mi][j][0] + b0, v01 = acc[mi][j][1] + b1;
            float v10 = acc[mi][j][2] + b0, v11 = acc[mi][j][3] + b1;
            if (sizeof(OutT) == 2) {
                *(__half2*)((__half*)C + (long)row * N + col)       = __floats2half2_rn(v00, v01);
                *(__half2*)((__half*)C + (long)(row + 8) * N + col) = __floats2half2_rn(v10, v11);
            } else {
                *(float2*)((float*)C + (long)row * N + col)       = make_float2(v00, v01);
                *(float2*)((float*)C + (long)(row + 8) * N + col) = make_float2(v10, v11);
            }
        }
    }
}
#define G_SMEM(MI) (3 * ((64 * (MI) + GBN) * GA_ST) * 2)

// ---------------- single-pass GEMM for K=128 (up-projections) ----------------
// Whole A strip (128x128) + B strip (64x128) loaded once; no pipeline, no
// per-iteration barriers. BM=128, BN=64, 256 threads, warp tile 32x32.
#define KA_ST 136   // 128 + 8 pad halves
#define K128_SMEM ((128 * KA_ST + 64 * KA_ST) * 2)   // 52224 B

__global__ __launch_bounds__(256, 3) void gemm_k128(
        const __half* __restrict__ A0, const __half* __restrict__ Bt0,
        const float* __restrict__ bi0, __half* __restrict__ C0,
        const __half* __restrict__ A1, const __half* __restrict__ Bt1,
        const float* __restrict__ bi1, __half* __restrict__ C1,
        int N) {
    const __half* A    = blockIdx.z ? A1 : A0;
    const __half* Bt   = blockIdx.z ? Bt1 : Bt0;
    const float*  bias = blockIdx.z ? bi1 : bi0;
    __half*       C    = blockIdx.z ? C1 : C0;

    extern __shared__ __half ksm[];
    __half* As = ksm;                 // [128][KA_ST]
    __half* Bs = ksm + 128 * KA_ST;   // [64][KA_ST]

    const int tid  = threadIdx.x;
    const int lane = tid & 31;
    const int wid  = tid >> 5;
    const int wm   = wid & 3;
    const int wn   = wid >> 2;
    const int g    = lane >> 2;
    const int qq   = lane & 3;

    const int a_lrow = 8 * ((lane >> 3) & 1) + (lane & 7);
    const int a_koff = 8 * (lane >> 4);
    const int b_lrow = 8 * ((lane >> 4) & 1) + (lane & 7);
    const int b_koff = 8 * ((lane >> 3) & 1);

    const int row0 = blockIdx.y * 128;
    const int col0 = blockIdx.x * 64;

    // load everything once
    #pragma unroll
    for (int i = tid; i < 2048; i += 256) {
        int row = i >> 4, c = i & 15;
        cp16(As + row * KA_ST + 8 * c, A + (long)(row0 + row) * 128 + 8 * c);
    }
    #pragma unroll
    for (int i = tid; i < 1024; i += 256) {
        int row = i >> 4, c = i & 15;
        cp16(Bs + row * KA_ST + 8 * c, Bt + (long)(col0 + row) * 128 + 8 * c);
    }
    CP_COMMIT();
    CP_WAIT(0);
    __syncthreads();

    float acc[2][4][4];
    #pragma unroll
    for (int mi = 0; mi < 2; mi++)
        #pragma unroll
        for (int j = 0; j < 4; j++)
            #pragma unroll
            for (int e = 0; e < 4; e++) acc[mi][j][e] = 0.0f;

    #pragma unroll
    for (int kk = 0; kk < 8; kk++) {
        unsigned a[2][4];
        #pragma unroll
        for (int mi = 0; mi < 2; mi++)
            ldsm_x4(a[mi][0], a[mi][1], a[mi][2], a[mi][3],
                    &As[(32 * wm + 16 * mi + a_lrow) * KA_ST + 16 * kk + a_koff]);
        unsigned bq[4][2];
        #pragma unroll
        for (int p = 0; p < 2; p++)
            ldsm_x4(bq[2 * p][0], bq[2 * p][1], bq[2 * p + 1][0], bq[2 * p + 1][1],
                    &Bs[(32 * wn + 16 * p + b_lrow) * KA_ST + 16 * kk + b_koff]);
        #pragma unroll
        for (int j = 0; j < 4; j++) {
            mma_f16(acc[0][j], a[0], bq[j]);
            mma_f16(acc[1][j], a[1], bq[j]);
        }
    }

    #pragma unroll
    for (int mi = 0; mi < 2; mi++) {
        int row = row0 + 32 * wm + 16 * mi + g;
        #pragma unroll
        for (int j = 0; j < 4; j++) {
            int col = col0 + 32 * wn + 8 * j + 2 * qq;
            float b0 = bias[col], b1 = bias[col + 1];
            *(__half2*)&C[(long)row * N + col] =
                __floats2half2_rn(acc[mi][j][0] + b0, acc[mi][j][1] + b1);
            *(__half2*)&C[(long)(row + 8) * N + col] =
                __floats2half2_rn(acc[mi][j][2] + b0, acc[mi][j][3] + b1);
        }
    }
}

// ---------------- fused prep: weight transpose+convert AND x conversion ----------------
// blocks [0,1536): transpose+convert weights; blocks [1536,5632): convert x.
__global__ void prep_all(const float* __restrict__ x,
                         const float* __restrict__ wdk, const float* __restrict__ wdv,
                         const float* __restrict__ wuk, const float* __restrict__ wuv,
                         const float* __restrict__ wo,
                         __half* __restrict__ xh,
                         __half* __restrict__ wdkT, __half* __restrict__ wdvT,
                         __half* __restrict__ wukT, __half* __restrict__ wuvT,
                         __half* __restrict__ woT) {
    __shared__ float tile[32][33];
    int id = blockIdx.x;
    int tid = threadIdx.x;
    if (id >= 1536) {
        int i = (id - 1536) * 256 + tid;
        float4 v = ((const float4*)x)[i];
        ((__half2*)xh)[2 * i]     = __floats2half2_rn(v.x, v.y);
        ((__half2*)xh)[2 * i + 1] = __floats2half2_rn(v.z, v.w);
        return;
    }
    const float* src; __half* dst; int R, Cn, bx, by;
    if (id < 256) {
        int w = id >> 7, rm = id & 127;
        src = w ? wdv : wdk; dst = w ? wdvT : wdkT;
        R = 1024; Cn = 128; bx = rm & 3; by = rm >> 2;
    } else if (id < 512) {
        int w = (id - 256) >> 7, rm = (id - 256) & 127;
        src = w ? wuv : wuk; dst = w ? wuvT : wukT;
        R = 128; Cn = 1024; bx = rm & 31; by = rm >> 5;
    } else {
        int rm = id - 512;
        src = wo; dst = woT;
        R = 1024; Cn = 1024; bx = rm & 31; by = rm >> 5;
    }
    int c0 = bx * 32, r0 = by * 32;
    int tx = tid & 31, ty = tid >> 5;
    #pragma unroll
    for (int i = 0; i < 4; i++)
        tile[ty + 8 * i][tx] = src[(long)(r0 + ty + 8 * i) * Cn + c0 + tx];
    __syncthreads();
    #pragma unroll
    for (int i = 0; i < 4; i++)
        dst[(long)(c0 + ty + 8 * i) * R + r0 + tx] = __float2half(tile[tx][ty + 8 * i]);
}

// ---------------- RoPE + head split + V transpose ----------------
#define QSCL 0.18033688011112042f   // 0.125 * log2(e)
#define VS_T_ST 68
__global__ void prepare_qkv(const __half* __restrict__ xh,
                            const __half* __restrict__ kf,
                            const __half* __restrict__ vf,
                            __half* __restrict__ qh,
                            __half* __restrict__ kh,
                            __half* __restrict__ vt) {
    __shared__ __half vs[64][VS_T_ST];
    const int tid = threadIdx.x;
    const int t0  = blockIdx.x * 64;
    const int bh  = blockIdx.y;
    const int b   = bh >> 4;
    const int h   = bh & 15;

    const int d   = tid & 63;
    const int tl0 = tid >> 6;
    const int i2  = d & 31;

    float inv_freq = exp2f(-(float)i2 * 0.41524101186092f);
    float sv, cv, S4, C4;
    sincosf((float)(t0 + tl0) * inv_freq, &sv, &cv);
    sincosf(4.0f * inv_freq, &S4, &C4);

    #pragma unroll
    for (int it = 0; it < 16; it++) {
        int tl = tl0 + 4 * it;
        int t = t0 + tl;
        long src = ((long)(b * Tc + t)) * Dc + h * DHc + d;

        float xv = __half2float(xh[src]);
        float xr = (d < 32) ? -__half2float(xh[src + 32]) : __half2float(xh[src - 32]);
        long dst = ((long)bh * Tc + t) * DHc + d;
        qh[dst] = __float2half((xv * cv + xr * sv) * QSCL);

        float kv = __half2float(kf[src]);
        float kr = (d < 32) ? -__half2float(kf[src + 32]) : __half2float(kf[src - 32]);
        kh[dst] = __float2half(kv * cv + kr * sv);

        vs[d][tl] = vf[src];

        float c2 = cv * C4 - sv * S4;
        float s2 = sv * C4 + cv * S4;
        cv = c2; sv = s2;
    }
    __syncthreads();
    #pragma unroll
    for (int it = 0; it < 16; it++) {
        int idx = it * 256 + tid;
        int dd = idx >> 6, tl = idx & 63;
        vt[((long)bh * DHc + dd) * Tc + t0 + tl] = vs[dd][tl];
    }
}

// ---------------- flash attention: 4 warps x m32, ldmatrix, log2 softmax ----------------
#define KS_ST 72
#define VT_ST 72
#define ATT_BUF_HALVES (64 * KS_ST + 64 * VT_ST)
#define ATT_SMEM_BYTES (3 * ATT_BUF_HALVES * 2)

__global__ __launch_bounds__(128, 2) void attn_kernel(
        const __half* __restrict__ qh,
        const __half* __restrict__ kh,
        const __half* __restrict__ vt,
        __half* __restrict__ out) {
    extern __shared__ __half sma[];

    const int tid  = threadIdx.x;
    const int lane = tid & 31;
    const int w    = tid >> 5;
    const int g    = lane >> 2;
    const int qq   = lane & 3;

    const int b_lrow = 8 * ((lane >> 4) & 1) + (lane & 7);
    const int b_koff = 8 * ((lane >> 3) & 1);

    const int bh = blockIdx.y;
    const int b  = bh >> 4;
    const int h  = bh & 15;
    const int t0 = blockIdx.x * 128;

    const __half* qp = qh + ((long)bh * Tc + t0) * DHc;
    const __half* kp = kh + (long)bh * Tc * DHc;
    const __half* vp = vt + (long)bh * DHc * Tc;

    unsigned qa[4][2][4];
    #pragma unroll
    for (int kk = 0; kk < 4; kk++)
        #pragma unroll
        for (int mt = 0; mt < 2; mt++) {
            int r0 = 32 * w + 16 * mt;
            qa[kk][mt][0] = *(const unsigned*)&qp[(r0 + g    ) * 64 + 16 * kk + 2 * qq];
            qa[kk][mt][1] = *(const unsigned*)&qp[(r0 + g + 8) * 64 + 16 * kk + 2 * qq];
            qa[kk][mt][2] = *(const unsigned*)&qp[(r0 + g    ) * 64 + 16 * kk + 2 * qq + 8];
            qa[kk][mt][3] = *(const unsigned*)&qp[(r0 + g + 8) * 64 + 16 * kk + 2 * qq + 8];
        }

    auto issue = [&](int tile) {
        __half* Kd = sma + (tile % 3) * ATT_BUF_HALVES;
        __half* Vd = Kd + 64 * KS_ST;
        int kt = tile * 64;
        #pragma unroll
        for (int i = tid; i < 512; i += 128) {
            int r = i >> 3, c = i & 7;
            cp16(Kd + r * KS_ST + 8 * c, kp + (long)(kt + r) * 64 + 8 * c);
            cp16(Vd + r * VT_ST + 8 * c, vp + (long)r * Tc + kt + 8 * c);
        }
    };

    float o[2][8][4];
    #pragma unroll
    for (int mt = 0; mt < 2; mt++)
        #pragma unroll
        for (int j = 0; j < 8; j++)
            #pragma unroll
            for (int e = 0; e < 4; e++) o[mt][j][e] = 0.0f;
    float m_i[2][2] = {{-1e30f, -1e30f}, {-1e30f, -1e30f}};
    float l_i[2][2] = {{0.0f, 0.0f}, {0.0f, 0.0f}};

    issue(0); CP_COMMIT();
    issue(1); CP_COMMIT();

    for (int it = 0; it < 32; it++) {
        CP_WAIT(1);
        __syncthreads();
        if (it + 2 < 32) issue(it + 2);
        CP_COMMIT();

        const __half* Ku = sma + (it % 3) * ATT_BUF_HALVES;
        const __half* Vu = Ku + 64 * KS_ST;

        float s[2][8][4];
        #pragma unroll
        for (int mt = 0; mt < 2; mt++)
            #pragma unroll
            for (int j = 0; j < 8; j++)
                #pragma unroll
                for (int e = 0; e < 4; e++) s[mt][j][e] = 0.0f;
        #pragma unroll
        for (int kk = 0; kk < 4; kk++) {
            unsigned bq[8][2];
            #pragma unroll
            for (int p = 0; p < 4; p++)
                ldsm_x4(bq[2 * p][0], bq[2 * p][1], bq[2 * p + 1][0], bq[2 * p + 1][1],
                        &Ku[(16 * p + b_lrow) * KS_ST + 16 * kk + b_koff]);
            #pragma unroll
            for (int j = 0; j < 8; j++) {
                mma_f16(s[0][j], qa[kk][0], bq[j]);
                mma_f16(s[1][j], qa[kk][1], bq[j]);
            }
        }

        #pragma unroll
        for (int mt = 0; mt < 2; mt++)
            #pragma unroll
            for (int hh = 0; hh < 2; hh++) {
                float mt_ = -1e30f;
                #pragma unroll
                for (int j = 0; j < 8; j++)
                    mt_ = fmaxf(mt_, fmaxf(s[mt][j][2 * hh], s[mt][j][2 * hh + 1]));
                mt_ = fmaxf(mt_, __shfl_xor_sync(0xffffffffu, mt_, 1));
                mt_ = fmaxf(mt_, __shfl_xor_sync(0xffffffffu, mt_, 2));

                float mnew = fmaxf(m_i[mt][hh], mt_);
                float corr = fexp2(m_i[mt][hh] - mnew);
                float lsum = 0.0f;
                #pragma unroll
                for (int j = 0; j < 8; j++) {
                    float p0 = fexp2(s[mt][j][2 * hh]     - mnew);
                    float p1 = fexp2(s[mt][j][2 * hh + 1] - mnew);
                    s[mt][j][2 * hh]     = p0;
                    s[mt][j][2 * hh + 1] = p1;
                    lsum += p0 + p1;
                }
                lsum += __shfl_xor_sync(0xffffffffu, lsum, 1);
                lsum += __shfl_xor_sync(0xffffffffu, lsum, 2);

                l_i[mt][hh] = l_i[mt][hh] * corr + lsum;
                m_i[mt][hh] = mnew;
                #pragma unroll
                for (int j = 0; j < 8; j++) {
                    o[mt][j][2 * hh]     *= corr;
                    o[mt][j][2 * hh + 1] *= corr;
                }
            }

        #pragma unroll
        for (int kk = 0; kk < 4; kk++) {
            unsigned pa[2][4];
            #pragma unroll
            for (int mt = 0; mt < 2; mt++) {
                pa[mt][0] = pack_h2(s[mt][2 * kk][0],     s[mt][2 * kk][1]);
                pa[mt][1] = pack_h2(s[mt][2 * kk][2],     s[mt][2 * kk][3]);
                pa[mt][2] = pack_h2(s[mt][2 * kk + 1][0], s[mt][2 * kk + 1][1]);
                pa[mt][3] = pack_h2(s[mt][2 * kk + 1][2], s[mt][2 * kk + 1][3]);
            }
            unsigned bq[8][2];
            #pragma unroll
            for (int p = 0; p < 4; p++)
                ldsm_x4(bq[2 * p][0], bq[2 * p][1], bq[2 * p + 1][0], bq[2 * p + 1][1],
                        &Vu[(16 * p + b_lrow) * VT_ST + 16 * kk + b_koff]);
            #pragma unroll
            for (int j = 0; j < 8; j++) {
                mma_f16(o[0][j], pa[0], bq[j]);
                mma_f16(o[1][j], pa[1], bq[j]);
            }
        }
    }

    #pragma unroll
    for (int mt = 0; mt < 2; mt++) {
        float inv0 = 1.0f / l_i[mt][0];
        float inv1 = 1.0f / l_i[mt][1];
        int t_r0 = t0 + 32 * w + 16 * mt + g;
        long base0 = ((long)b * Tc + t_r0) * Dc + h * DHc;
        long base1 = ((long)b * Tc + t_r0 + 8) * Dc + h * DHc;
        #pragma unroll
        for (int j = 0; j < 8; j++) {
            int col = 8 * j + 2 * qq;
            *(__half2*)&out[base0 + col] = __floats2half2_rn(o[mt][j][0] * inv0, o[mt][j][1] * inv0);
            *(__half2*)&out[base1 + col] = __floats2half2_rn(o[mt][j][2] * inv1, o[mt][j][3] * inv1);
        }
    }
}

// ---------------- launch ----------------
extern "C" void kernel_launch(void* const* d_in, const int* in_sizes, int n_in,
                              void* d_out, int out_size) {
    const float* x    = (const float*)d_in[0];
    const float* w_dk = (const float*)d_in[1];
    const float* b_dk = (const float*)d_in[2];
    const float* w_dv = (const float*)d_in[3];
    const float* b_dv = (const float*)d_in[4];
    const float* w_uk = (const float*)d_in[5];
    const float* b_uk = (const float*)d_in[6];
    const float* w_uv = (const float*)d_in[7];
    const float* b_uv = (const float*)d_in[8];
    const float* w_o  = (const float*)d_in[9];
    const float* b_o  = (const float*)d_in[10];
    float* out = (float*)d_out;

    __half *xh, *wdkT, *wdvT, *wukT, *wuvT, *woT, *ck, *cv, *kf, *vf, *qh, *kh, *vt, *ao;
    cudaGetSymbolAddress((void**)&xh,   g_xh);
    cudaGetSymbolAddress((void**)&wdkT, g_wdkT);
    cudaGetSymbolAddress((void**)&wdvT, g_wdvT);
    cudaGetSymbolAddress((void**)&wukT, g_wukT);
    cudaGetSymbolAddress((void**)&wuvT, g_wuvT);
    cudaGetSymbolAddress((void**)&woT,  g_woT);
    cudaGetSymbolAddress((void**)&ck,   g_ck);
    cudaGetSymbolAddress((void**)&cv,   g_cv);
    cudaGetSymbolAddress((void**)&kf,   g_kf);
    cudaGetSymbolAddress((void**)&vf,   g_vf);
    cudaGetSymbolAddress((void**)&qh,   g_qh);
    cudaGetSymbolAddress((void**)&kh,   g_kh);
    cudaGetSymbolAddress((void**)&vt,   g_vt);
    cudaGetSymbolAddress((void**)&ao,   g_ao);

    static int attrs_set = 0;
    if (!attrs_set) {
        cudaFuncSetAttribute((const void*)mma_gemm<1, __half>, cudaFuncAttributeMaxDynamicSharedMemorySize, G_SMEM(1));
        cudaFuncSetAttribute((const void*)mma_gemm<2, float>,  cudaFuncAttributeMaxDynamicSharedMemorySize, G_SMEM(2));
        cudaFuncSetAttribute((const void*)gemm_k128, cudaFuncAttributeMaxDynamicSharedMemorySize, K128_SMEM);
        cudaFuncSetAttribute((const void*)attn_kernel, cudaFuncAttributeMaxDynamicSharedMemorySize, ATT_SMEM_BYTES);
        attrs_set = 1;
    }

    // fused prep: weights transpose+convert (blocks 0..1535) + x convert (1536..5631)
    prep_all<<<5632, 256>>>(x, w_dk, w_dv, w_uk, w_uv, w_o,
                            xh, wdkT, wdvT, wukT, wuvT, woT);

    // down-projections: (BT x 1024) @ (1024 x 128) -> fp16 ck/cv  [BM=64: 256 CTAs]
    mma_gemm<1, __half><<<dim3(Cc / GBN, BT / 64, 2), 256, G_SMEM(1)>>>(
        xh, wdkT, b_dk, ck, xh, wdvT, b_dv, cv, BT, Cc, Dc);

    // up-projections: (BT x 128) @ (128 x 1024), K=128 single pass -> fp16 kf/vf
    gemm_k128<<<dim3(Dc / 64, BT / 128, 2), 256, K128_SMEM>>>(
        ck, wukT, b_uk, kf, cv, wuvT, b_uv, vf, Dc);

    // RoPE + head split + V transpose (Q pre-scaled)
    prepare_qkv<<<dim3(Tc / 64, Bc * Hc), 256>>>(xh, kf, vf, qh, kh, vt);

    // attention: 128 threads, 4 warps x m32
    attn_kernel<<<dim3(Tc / 128, Bc * Hc), 128, ATT_SMEM_BYTES>>>(qh, kh, vt, ao);

    // output projection: (BT x 1024) @ (1024 x 1024) -> fp32 out
    mma_gemm<2, float><<<dim3(Dc / GBN, BT / 128, 1), 256, G_SMEM(2)>>>(
        ao, woT, b_o, out, ao, woT, b_o, out, BT, Dc, Dc);
}